// round 7
// baseline (speedup 1.0000x reference)
#include <cuda_runtime.h>
#include <cuda_bf16.h>
#include <math.h>
#include <float.h>
#include <stdint.h>

#define BB 8
#define TT 4096
#define HH 128
#define NBLK 6
#define KK 20
#define BT (BB*TT)   // 32768
#define SX 132       // activation tile stride (floats)
#define BSTR 136     // B chunk stride (floats)

typedef unsigned long long u64;

// packed f32x2 helpers
#define FMA2(d, a, b, c) \
    asm("fma.rn.f32x2 %0, %1, %2, %3;" : "=l"(d) : "l"(a), "l"(b), "l"(c))
#define MUL2(d, a, b) \
    asm("mul.rn.f32x2 %0, %1, %2;" : "=l"(d) : "l"(a), "l"(b))
#define ADD2(d, a, b) \
    asm("add.rn.f32x2 %0, %1, %2;" : "=l"(d) : "l"(a), "l"(b))
#define BCAST2(d, s) \
    asm("mov.b64 %0, {%1, %1};" : "=l"(d) : "r"(s))
#define UNPK2(lo, hi, s) \
    asm("mov.b64 {%0, %1}, %2;" : "=r"(lo), "=r"(hi) : "l"(s))

__device__ __forceinline__ u64 pack2(float a, float b) {
    u64 r;
    asm("mov.b64 %0, {%1, %2};" : "=l"(r) : "r"(__float_as_uint(a)), "r"(__float_as_uint(b)));
    return r;
}
__device__ __forceinline__ u64 bcast2f(float a) {
    u64 r; BCAST2(r, __float_as_uint(a)); return r;
}

// tf32 mma (sm_80+ PTX, valid at target sm_103)
#define MMA_TF32(d, a, b) \
    asm volatile("mma.sync.aligned.m16n8k8.row.col.f32.tf32.tf32.f32 " \
        "{%0,%1,%2,%3}, {%4,%5,%6,%7}, {%8,%9}, {%0,%1,%2,%3};" \
        : "+f"((d)[0]), "+f"((d)[1]), "+f"((d)[2]), "+f"((d)[3]) \
        : "r"((a)[0]), "r"((a)[1]), "r"((a)[2]), "r"((a)[3]), \
          "r"((b)[0]), "r"((b)[1]))

__device__ __forceinline__ uint32_t tf32_hi(float v) {
    uint32_t h; asm("cvt.rna.tf32.f32 %0, %1;" : "=r"(h) : "f"(v));
    return h;
}

// ---------------- scratch (device globals; no allocation) ----------------
__device__ float g_net[BT * HH];   // 16 MB
__device__ float g_att[BT * HH];   // 16 MB
__device__ int   g_idx[BT * KK];
__device__ float g_dis[BT * KK];
__device__ float g_bprep[NBLK * 48 * 4096];   // 4.7 MB

// ======================= KNN ============================================
// 128 threads/block, 1 query/thread, packed-pair candidate scan.
__device__ __forceinline__ void topk_insert(float* bd, int* bi, float d, int idx)
{
    bd[KK-1] = d; bi[KK-1] = idx;
#pragma unroll
    for (int q2 = KK-1; q2 > 0; --q2) {
        if (bd[q2] < bd[q2-1]) {
            float td = bd[q2]; bd[q2] = bd[q2-1]; bd[q2-1] = td;
            int   ti = bi[q2]; bi[q2] = bi[q2-1]; bi[q2-1] = ti;
        }
    }
}

#define SIGNMASK2 0x8000000080000000ull

__global__ __launch_bounds__(128) void knn_kernel(const float* __restrict__ p)
{
    const int b   = blockIdx.y;
    const int tid = threadIdx.x;
    const int tt  = blockIdx.x * 128 + tid;
    const float* pb = p + (size_t)b * TT * 3;

    const float qx = pb[tt*3+0], qy = pb[tt*3+1], qz = pb[tt*3+2];
    const float sqq = qx*qx + qy*qy + qz*qz;
    const u64 qx2 = bcast2f(qx), qy2 = bcast2f(qy), qz2 = bcast2f(qz);
    const u64 NEG2 = bcast2f(-2.0f);

    float bd[KK];
    int   bi[KK];
#pragma unroll
    for (int k = 0; k < KK; ++k) { bd[k] = FLT_MAX; bi[k] = 0; }
    u64 nt2 = bcast2f(-FLT_MAX);   // packed (sqq - bd[19]); e + nt < 0 -> candidate

    __shared__ ulonglong2 spXY[512];   // (x-pair, y-pair)
    __shared__ ulonglong2 spZW[512];   // (z-pair, |.|^2-pair)

    for (int s0 = 0; s0 < TT; s0 += 1024) {
        __syncthreads();
        for (int l = tid; l < 512; l += 128) {
            const float* q = pb + (size_t)(s0 + 2*l) * 3;
            float x0 = q[0], y0 = q[1], z0 = q[2];
            float x1 = q[3], y1 = q[4], z1 = q[5];
            spXY[l] = make_ulonglong2(pack2(x0, x1), pack2(y0, y1));
            spZW[l] = make_ulonglong2(pack2(z0, z1),
                                      pack2(x0*x0 + y0*y0 + z0*z0,
                                            x1*x1 + y1*y1 + z1*z1));
        }
        __syncthreads();
#pragma unroll 4
        for (int l = 0; l < 512; ++l) {
            ulonglong2 xy = spXY[l];
            ulonglong2 zw = spZW[l];
            u64 d; MUL2(d, qz2, zw.x);
            FMA2(d, qy2, xy.y, d);
            FMA2(d, qx2, xy.x, d);
            u64 e; FMA2(e, d, NEG2, zw.y);     // d2' = |s|^2 - 2 q.s
            u64 t; ADD2(t, e, nt2);
            if (t & SIGNMASK2) {
                unsigned lo, hi; UNPK2(lo, hi, e);
                float d0 = __uint_as_float(lo) + sqq;
                if (d0 < bd[KK-1]) topk_insert(bd, bi, d0, s0 + 2*l);
                float d1 = __uint_as_float(hi) + sqq;
                if (d1 < bd[KK-1]) topk_insert(bd, bi, d1, s0 + 2*l + 1);
                nt2 = bcast2f(sqq - bd[KK-1]);
            }
        }
    }

    const size_t o = ((size_t)b * TT + tt) * KK;
#pragma unroll
    for (int k = 0; k < KK; ++k) {
        g_idx[o + k] = bi[k];
        g_dis[o + k] = sqrtf(fmaxf(bd[k], 1e-12f));
    }
}

// ======================= positional encoding ============================
__global__ __launch_bounds__(256) void pos_kernel(const float* __restrict__ p,
                                                  const float* __restrict__ W_pos,
                                                  const float* __restrict__ b_pos)
{
    int gid = blockIdx.x * 256 + threadIdx.x;
    int t = gid >> 7;
    int h = gid & 127;
    const float* pp = p + (size_t)t * 3;
    float v = b_pos[h];
    v = fmaf(pp[0], W_pos[h],        v);
    v = fmaf(pp[1], W_pos[HH + h],   v);
    v = fmaf(pp[2], W_pos[2*HH + h], v);
    g_net[gid] = v;
}

// ======================= attention (gather + softmax) ===================
__global__ __launch_bounds__(256) void attn_kernel(const float* __restrict__ p,
                                                   const float* __restrict__ wc,
                                                   const float* __restrict__ bc)
{
    const int warp = threadIdx.x >> 5;
    const int lane = threadIdx.x & 31;
    const int t  = blockIdx.x * 8 + warp;
    const int b  = t >> 12;
    const int tt = t & (TT - 1);
    const float* pb = p + (size_t)b * TT * 3;

    const float q0 = pb[tt*3+0], q1 = pb[tt*3+1], q2 = pb[tt*3+2];
    const float w0 = wc[0], w1 = wc[1], w2 = wc[2], w3 = wc[3];
    const float w4 = wc[4], w5 = wc[5], w6 = wc[6], bcv = bc[0];

    float s = -FLT_MAX;
    int   j = 0;
    if (lane < KK) {
        size_t o = (size_t)t * KK + lane;
        j = g_idx[o];
        float d = g_dis[o];
        const float* px = pb + (size_t)j * 3;
        s = bcv;
        s = fmaf(w0, d,     s);
        s = fmaf(w1, px[0], s);
        s = fmaf(w2, px[1], s);
        s = fmaf(w3, px[2], s);
        s = fmaf(w4, q0,    s);
        s = fmaf(w5, q1,    s);
        s = fmaf(w6, q2,    s);
    }
    float m = s;
#pragma unroll
    for (int off = 16; off; off >>= 1)
        m = fmaxf(m, __shfl_xor_sync(0xffffffffu, m, off));
    float e = (lane < KK) ? expf(s - m) : 0.0f;
    float sum = e;
#pragma unroll
    for (int off = 16; off; off >>= 1)
        sum += __shfl_xor_sync(0xffffffffu, sum, off);
    const float inv = 1.0f / sum;

    float4 acc = make_float4(0.f, 0.f, 0.f, 0.f);
    const float* nb = g_net + (size_t)b * TT * HH;
#pragma unroll
    for (int k = 0; k < KK; ++k) {
        float wk = __shfl_sync(0xffffffffu, e, k) * inv;
        int   jk = __shfl_sync(0xffffffffu, j, k);
        float4 v = *(const float4*)(nb + (size_t)jk * HH + lane * 4);
        acc.x = fmaf(wk, v.x, acc.x);
        acc.y = fmaf(wk, v.y, acc.y);
        acc.z = fmaf(wk, v.z, acc.z);
        acc.w = fmaf(wk, v.w, acc.w);
    }
    *(float4*)(g_att + (size_t)t * HH + lane * 4) = acc;
}

// ======================= weight prep ====================================
// 48 K16-chunk slots per block:
//   Wo: 0..7, W0: 8..23 (K=256), W1: 24..31, Ws: 32..47 (K=256)
__global__ __launch_bounds__(256) void prep_weights(
    const float* __restrict__ Wo, const float* __restrict__ W0,
    const float* __restrict__ W1, const float* __restrict__ Ws)
{
    const int blk = blockIdx.y;
    const int slot = blockIdx.x;
    const float* W; int ck;
    if (slot < 8)       { W = Wo + (size_t)blk*128*128; ck = slot; }
    else if (slot < 24) { W = W0 + (size_t)blk*256*128; ck = slot-8; }
    else if (slot < 32) { W = W1 + (size_t)blk*128*128; ck = slot-24; }
    else                { W = Ws + (size_t)blk*256*128; ck = slot-32; }
    float* img = g_bprep + ((size_t)blk*48 + slot)*4096;

    for (int idx = threadIdx.x; idx < 2048; idx += 256) {
        int kk = idx >> 7, n = idx & 127;
        float v = W[(size_t)(ck*16 + kk)*128 + n];
        uint32_t h = tf32_hi(v);
        float hv = __uint_as_float(h);
        uint32_t l = tf32_hi(v - hv);
        img[idx]        = hv;
        img[2048 + idx] = __uint_as_float(l);
    }
}

// ======================= tensor-core resnet =============================
__device__ __forceinline__ void init_acc(float acc[2][8][4],
                                         const float* __restrict__ bias,
                                         int nb, int tig)
{
#pragma unroll
    for (int j = 0; j < 8; ++j) {
        int col0 = nb + j*8 + 2*tig;
        float b0v = __ldg(bias + col0);
        float b1v = __ldg(bias + col0 + 1);
#pragma unroll
        for (int mt = 0; mt < 2; ++mt) {
            acc[mt][j][0] = b0v; acc[mt][j][1] = b1v;
            acc[mt][j][2] = b0v; acc[mt][j][3] = b1v;
        }
    }
}

template<bool RELU>
__device__ __forceinline__ void gemm_tc(
    const float* As, const float* __restrict__ prep, int nchunks,
    float acc[2][8][4], float* Bs, int tid, int rb, int nb)
{
    const int lane = tid & 31;
    const int gid = lane >> 2, tig = lane & 3;

    for (int c = 0; c < nchunks; ++c) {
        __syncthreads();
        const float* src = prep + (size_t)c * 4096;
#pragma unroll
        for (int i = 0; i < 2; ++i) {
            int idx4 = tid + i*256;                  // < 512
            int kk = idx4 >> 5, n4 = (idx4 & 31) << 2;
            *(float4*)(Bs + kk*BSTR + n4)             = *(const float4*)(src + idx4*4);
            *(float4*)(Bs + 16*BSTR + kk*BSTR + n4)   = *(const float4*)(src + 2048 + idx4*4);
        }
        __syncthreads();

#pragma unroll
        for (int ks = 0; ks < 2; ++ks) {
            const int k0 = c*16 + ks*8;
            uint32_t Ah[2][4], Al[2][4];
#pragma unroll
            for (int mt = 0; mt < 2; ++mt) {
                const int r0 = rb + mt*16 + gid;
                float f[4];
                f[0] = As[(size_t)r0*SX + k0 + tig];
                f[1] = As[(size_t)(r0+8)*SX + k0 + tig];
                f[2] = As[(size_t)r0*SX + k0 + tig + 4];
                f[3] = As[(size_t)(r0+8)*SX + k0 + tig + 4];
#pragma unroll
                for (int i = 0; i < 4; ++i) {
                    float v = RELU ? fmaxf(f[i], 0.0f) : f[i];
                    uint32_t h = tf32_hi(v);
                    Ah[mt][i] = h;
                    Al[mt][i] = tf32_hi(v - __uint_as_float(h));
                }
            }
#pragma unroll
            for (int j = 0; j < 8; ++j) {
                const int nbase = nb + j*8 + gid;
                const float* bk0 = Bs + (ks*8 + tig)*BSTR + nbase;
                const float* bk1 = Bs + (ks*8 + tig + 4)*BSTR + nbase;
                uint32_t bh[2], bl[2];
                bh[0] = __float_as_uint(bk0[0]);
                bh[1] = __float_as_uint(bk1[0]);
                bl[0] = __float_as_uint(bk0[16*BSTR]);
                bl[1] = __float_as_uint(bk1[16*BSTR]);
#pragma unroll
                for (int mt = 0; mt < 2; ++mt) {
                    MMA_TF32(acc[mt][j], Ah[mt], bh);
                    MMA_TF32(acc[mt][j], Al[mt], bh);
                    MMA_TF32(acc[mt][j], Ah[mt], bl);
                }
            }
        }
    }
}

template<bool RELU>
__device__ __forceinline__ void store_acc_smem(float acc[2][8][4], float* tile,
                                               int rb, int nb, int lane)
{
    const int gid = lane >> 2, tig = lane & 3;
#pragma unroll
    for (int mt = 0; mt < 2; ++mt) {
        const int rg = rb + mt*16 + gid;
#pragma unroll
        for (int j = 0; j < 8; ++j) {
            const int col0 = nb + j*8 + 2*tig;
            float v0 = acc[mt][j][0], v1 = acc[mt][j][1];
            float v2 = acc[mt][j][2], v3 = acc[mt][j][3];
            if (RELU) {
                v0 = fmaxf(v0, 0.f); v1 = fmaxf(v1, 0.f);
                v2 = fmaxf(v2, 0.f); v3 = fmaxf(v3, 0.f);
            }
            *(float2*)(tile + (size_t)rg*SX + col0)     = make_float2(v0, v1);
            *(float2*)(tile + (size_t)(rg+8)*SX + col0) = make_float2(v2, v3);
        }
    }
}

__global__ __launch_bounds__(256) void resnet_tc(
    int blk,
    const float* __restrict__ b0, const float* __restrict__ b1,
    const float* __restrict__ bo, int add_res)
{
    extern __shared__ float sm[];
    float* xs  = sm;                 // [128][SX] net (x)
    float* as_ = sm + 128*SX;        // [128][SX] a1
    float* hs  = sm + 2*128*SX;      // [128][SX] att, then relu(h)
    float* Bs  = sm + 3*128*SX;      // [32][BSTR] hi+lo chunk

    const int tid = threadIdx.x;
    const int wid = tid >> 5, lane = tid & 31;
    const int rb = (wid & 3) * 32;
    const int nb = (wid >> 2) * 64;
    const int gid = lane >> 2, tig = lane & 3;
    const size_t t0 = (size_t)blockIdx.x * 128;
    const float* prep = g_bprep + (size_t)blk * 48 * 4096;

    for (int q = tid; q < 128 * 32; q += 256) {
        int r = q >> 5, c = (q & 31) << 2;
        *(float4*)(xs + r * SX + c) = *(const float4*)(g_net + (t0 + r) * HH + c);
        *(float4*)(hs + r * SX + c) = *(const float4*)(g_att + (t0 + r) * HH + c);
    }

    float acc[2][8][4];

    // ---- GEMM1: a1 = att @ Wo^T + bo -> as_
    init_acc(acc, bo, nb, tig);
    gemm_tc<false>(hs, prep + 0*4096, 8, acc, Bs, tid, rb, nb);
    store_acc_smem<false>(acc, as_, rb, nb, lane);

    // ---- GEMM2: h = relu(relu([x|a1]) @ W0 + b0) -> hs
    init_acc(acc, b0, nb, tig);
    gemm_tc<true>(xs,  prep + 8*4096,  8, acc, Bs, tid, rb, nb);
    gemm_tc<true>(as_, prep + 16*4096, 8, acc, Bs, tid, rb, nb);
    __syncthreads();
    store_acc_smem<true>(acc, hs, rb, nb, lane);

    // ---- GEMM3+4: out = h @ W1^T + b1 + [x|a1] @ Ws^T [+ residual x]
    init_acc(acc, b1, nb, tig);
    gemm_tc<false>(hs,  prep + 24*4096, 8, acc, Bs, tid, rb, nb);
    gemm_tc<false>(xs,  prep + 32*4096, 8, acc, Bs, tid, rb, nb);
    gemm_tc<false>(as_, prep + 40*4096, 8, acc, Bs, tid, rb, nb);

#pragma unroll
    for (int mt = 0; mt < 2; ++mt) {
        const int rg = rb + mt*16 + gid;
#pragma unroll
        for (int j = 0; j < 8; ++j) {
            const int col0 = nb + j*8 + 2*tig;
            float v0 = acc[mt][j][0], v1 = acc[mt][j][1];
            float v2 = acc[mt][j][2], v3 = acc[mt][j][3];
            if (add_res) {
                float2 r0 = *(const float2*)(xs + (size_t)rg*SX + col0);
                float2 r1 = *(const float2*)(xs + (size_t)(rg+8)*SX + col0);
                v0 += r0.x; v1 += r0.y; v2 += r1.x; v3 += r1.y;
            }
            *(float2*)(g_net + (t0 + rg) * HH + col0)     = make_float2(v0, v1);
            *(float2*)(g_net + (t0 + rg + 8) * HH + col0) = make_float2(v2, v3);
        }
    }
}

// ======================= final projection (scalar, FFMA2) ===============
__device__ __forceinline__ void init_bias_f(u64 acc[8][4], const float* __restrict__ bias, int nb)
{
    ulonglong2 q0 = *(const ulonglong2*)(bias + nb);
    ulonglong2 q1 = *(const ulonglong2*)(bias + nb + 4);
#pragma unroll
    for (int r = 0; r < 8; ++r) {
        acc[r][0] = q0.x; acc[r][1] = q0.y; acc[r][2] = q1.x; acc[r][3] = q1.y;
    }
}

__global__ __launch_bounds__(256) void final_kernel(const float* __restrict__ W_c,
                                                    const float* __restrict__ b_c,
                                                    float* __restrict__ out)
{
    extern __shared__ float sm[];
    float* xs = sm;              // [128][SX]
    float* ws = sm + 128 * SX;   // [32][128]

    const int tid = threadIdx.x;
    const int tx = tid & 15;
    const int ty = tid >> 4;
    const int nb = tx * 8;
    const int rb = ty * 8;
    const size_t t0 = (size_t)blockIdx.x * 128;

    for (int q = tid; q < 128 * 32; q += 256) {
        int r = q >> 5, c = (q & 31) << 2;
        *(float4*)(xs + r * SX + c) = *(const float4*)(g_net + (t0 + r) * HH + c);
    }

    u64 acc[8][4];
    init_bias_f(acc, b_c, nb);

    for (int kt = 0; kt < 128; kt += 32) {
        __syncthreads();
        for (int q = tid; q < 1024; q += 256) {
            int kk = q >> 5, c = (q & 31) << 2;
            *(float4*)(ws + kk * 128 + c) = *(const float4*)(W_c + (size_t)(kt + kk) * 128 + c);
        }
        __syncthreads();
#pragma unroll 1
        for (int k4 = 0; k4 < 8; ++k4) {
            float4 a4[8];
#pragma unroll
            for (int r = 0; r < 8; ++r)
                a4[r] = *(const float4*)(xs + (rb + r) * SX + kt + k4 * 4);
#pragma unroll
            for (int j = 0; j < 4; ++j) {
                int kk = k4 * 4 + j;
                ulonglong2 b0v = *(const ulonglong2*)(ws + kk * 128 + nb);
                ulonglong2 b1v = *(const ulonglong2*)(ws + kk * 128 + nb + 4);
#pragma unroll
                for (int r = 0; r < 8; ++r) {
                    float a = ((const float*)&a4[r])[j];
                    u64 aa; BCAST2(aa, __float_as_uint(a));
                    FMA2(acc[r][0], aa, b0v.x, acc[r][0]);
                    FMA2(acc[r][1], aa, b0v.y, acc[r][1]);
                    FMA2(acc[r][2], aa, b1v.x, acc[r][2]);
                    FMA2(acc[r][3], aa, b1v.y, acc[r][3]);
                }
            }
        }
    }
#pragma unroll
    for (int r = 0; r < 8; ++r) {
        *(ulonglong2*)(out + (t0 + rb + r) * HH + nb)     = make_ulonglong2(acc[r][0], acc[r][1]);
        *(ulonglong2*)(out + (t0 + rb + r) * HH + nb + 4) = make_ulonglong2(acc[r][2], acc[r][3]);
    }
}

// ======================= launch =========================================
extern "C" void kernel_launch(void* const* d_in, const int* in_sizes, int n_in,
                              void* d_out, int out_size)
{
    const float* p      = (const float*)d_in[0];
    const float* W_pos  = (const float*)d_in[1];
    const float* b_pos  = (const float*)d_in[2];
    const float* blk_W0 = (const float*)d_in[3];
    const float* blk_b0 = (const float*)d_in[4];
    const float* blk_W1 = (const float*)d_in[5];
    const float* blk_b1 = (const float*)d_in[6];
    const float* blk_Ws = (const float*)d_in[7];
    const float* att_Wc = (const float*)d_in[8];
    const float* att_bc = (const float*)d_in[9];
    const float* att_Wo = (const float*)d_in[10];
    const float* att_bo = (const float*)d_in[11];
    const float* W_c    = (const float*)d_in[12];
    const float* b_c    = (const float*)d_in[13];
    float* out = (float*)d_out;

    const int RES_SMEM = (3 * 128 * SX + 32 * BSTR) * 4;   // 220,160 B
    const int FIN_SMEM = (128 * SX + 32 * 128) * 4;        //  83,968 B
    cudaFuncSetAttribute(resnet_tc,   cudaFuncAttributeMaxDynamicSharedMemorySize, RES_SMEM);
    cudaFuncSetAttribute(final_kernel, cudaFuncAttributeMaxDynamicSharedMemorySize, FIN_SMEM);

    prep_weights<<<dim3(48, NBLK), 256>>>(att_Wo, blk_W0, blk_W1, blk_Ws);
    knn_kernel<<<dim3(TT / 128, BB), 128>>>(p);
    pos_kernel<<<(BT * HH) / 256, 256>>>(p, W_pos, b_pos);

    for (int i = 0; i < NBLK; ++i) {
        attn_kernel<<<BT / 8, 256>>>(p, att_Wc + (size_t)i * 7, att_bc + i);
        resnet_tc<<<BT / 128, 256, RES_SMEM>>>(
            i, blk_b0 + (size_t)i * 128, blk_b1 + (size_t)i * 128,
            att_bo + (size_t)i * 128, i > 0 ? 1 : 0);
    }
    final_kernel<<<BT / 128, 256, FIN_SMEM>>>(W_c, b_c, out);
}

// round 8
// speedup vs baseline: 1.6609x; 1.6609x over previous
#include <cuda_runtime.h>
#include <cuda_bf16.h>
#include <math.h>
#include <float.h>
#include <stdint.h>

#define BB 8
#define TT 4096
#define HH 128
#define NBLK 6
#define KK 20
#define BT (BB*TT)   // 32768
#define SX 132       // activation tile stride (floats)
#define BSTR 136     // B chunk stride (floats)

typedef unsigned long long u64;

// packed f32x2 helpers (scalar kernels)
#define FMA2(d, a, b, c) \
    asm("fma.rn.f32x2 %0, %1, %2, %3;" : "=l"(d) : "l"(a), "l"(b), "l"(c))
#define BCAST2(d, s) \
    asm("mov.b64 %0, {%1, %1};" : "=l"(d) : "r"(s))

// tf32 mma (sm_80+ PTX, valid at target sm_103)
#define MMA_TF32(d, a, b) \
    asm volatile("mma.sync.aligned.m16n8k8.row.col.f32.tf32.tf32.f32 " \
        "{%0,%1,%2,%3}, {%4,%5,%6,%7}, {%8,%9}, {%0,%1,%2,%3};" \
        : "+f"((d)[0]), "+f"((d)[1]), "+f"((d)[2]), "+f"((d)[3]) \
        : "r"((a)[0]), "r"((a)[1]), "r"((a)[2]), "r"((a)[3]), \
          "r"((b)[0]), "r"((b)[1]))

__device__ __forceinline__ uint32_t tf32_hi(float v) {
    uint32_t h; asm("cvt.rna.tf32.f32 %0, %1;" : "=r"(h) : "f"(v));
    return h;
}

// ---------------- scratch (device globals; no allocation) ----------------
__device__ float g_net[BT * HH];   // 16 MB
__device__ float g_att[BT * HH];   // 16 MB
__device__ int   g_idx[BT * KK];
__device__ float g_dis[BT * KK];
__device__ float g_bprep[NBLK * 48 * 4096];   // 4.7 MB

// ======================= KNN (round-5 scalar version) ===================
__global__ __launch_bounds__(128) void knn_kernel(const float* __restrict__ p)
{
    const int b  = blockIdx.y;
    const int tt = blockIdx.x * 128 + threadIdx.x;
    const float* pb = p + (size_t)b * TT * 3;

    const float qx = pb[tt*3 + 0];
    const float qy = pb[tt*3 + 1];
    const float qz = pb[tt*3 + 2];
    const float sqq = (qx*qx + qy*qy) + qz*qz;

    float bd[KK];
    int   bi[KK];
#pragma unroll
    for (int k = 0; k < KK; ++k) { bd[k] = FLT_MAX; bi[k] = 0; }

    __shared__ float4 sp[1024];   // x,y,z,|.|^2

    for (int s0 = 0; s0 < TT; s0 += 1024) {
        __syncthreads();
        for (int l = threadIdx.x; l < 1024; l += 128) {
            const float* q = pb + (size_t)(s0 + l) * 3;
            float x = q[0], y = q[1], z = q[2];
            sp[l] = make_float4(x, y, z, (x*x + y*y) + z*z);
        }
        __syncthreads();
#pragma unroll 4
        for (int l = 0; l < 1024; ++l) {
            float4 v = sp[l];
            float dot = qx*v.x + qy*v.y + qz*v.z;
            float d2  = sqq + v.w - 2.0f * dot;
            if (d2 < bd[KK-1]) {
                bd[KK-1] = d2; bi[KK-1] = s0 + l;
#pragma unroll
                for (int q2 = KK-1; q2 > 0; --q2) {
                    if (bd[q2] < bd[q2-1]) {
                        float td = bd[q2]; bd[q2] = bd[q2-1]; bd[q2-1] = td;
                        int   ti = bi[q2]; bi[q2] = bi[q2-1]; bi[q2-1] = ti;
                    }
                }
            }
        }
    }

    const size_t o = ((size_t)b * TT + tt) * KK;
#pragma unroll
    for (int k = 0; k < KK; ++k) {
        g_idx[o + k] = bi[k];
        g_dis[o + k] = sqrtf(fmaxf(bd[k], 1e-12f));
    }
}

// ======================= positional encoding ============================
__global__ __launch_bounds__(256) void pos_kernel(const float* __restrict__ p,
                                                  const float* __restrict__ W_pos,
                                                  const float* __restrict__ b_pos)
{
    int gid = blockIdx.x * 256 + threadIdx.x;
    int t = gid >> 7;
    int h = gid & 127;
    const float* pp = p + (size_t)t * 3;
    float v = b_pos[h];
    v = fmaf(pp[0], W_pos[h],        v);
    v = fmaf(pp[1], W_pos[HH + h],   v);
    v = fmaf(pp[2], W_pos[2*HH + h], v);
    g_net[gid] = v;
}

// ======================= attention (gather + softmax) ===================
__global__ __launch_bounds__(256) void attn_kernel(const float* __restrict__ p,
                                                   const float* __restrict__ wc,
                                                   const float* __restrict__ bc)
{
    const int warp = threadIdx.x >> 5;
    const int lane = threadIdx.x & 31;
    const int t  = blockIdx.x * 8 + warp;
    const int b  = t >> 12;
    const int tt = t & (TT - 1);
    const float* pb = p + (size_t)b * TT * 3;

    const float q0 = pb[tt*3+0], q1 = pb[tt*3+1], q2 = pb[tt*3+2];
    const float w0 = wc[0], w1 = wc[1], w2 = wc[2], w3 = wc[3];
    const float w4 = wc[4], w5 = wc[5], w6 = wc[6], bcv = bc[0];

    float s = -FLT_MAX;
    int   j = 0;
    if (lane < KK) {
        size_t o = (size_t)t * KK + lane;
        j = g_idx[o];
        float d = g_dis[o];
        const float* px = pb + (size_t)j * 3;
        s = bcv;
        s = fmaf(w0, d,     s);
        s = fmaf(w1, px[0], s);
        s = fmaf(w2, px[1], s);
        s = fmaf(w3, px[2], s);
        s = fmaf(w4, q0,    s);
        s = fmaf(w5, q1,    s);
        s = fmaf(w6, q2,    s);
    }
    float m = s;
#pragma unroll
    for (int off = 16; off; off >>= 1)
        m = fmaxf(m, __shfl_xor_sync(0xffffffffu, m, off));
    float e = (lane < KK) ? expf(s - m) : 0.0f;
    float sum = e;
#pragma unroll
    for (int off = 16; off; off >>= 1)
        sum += __shfl_xor_sync(0xffffffffu, sum, off);
    const float inv = 1.0f / sum;

    float4 acc = make_float4(0.f, 0.f, 0.f, 0.f);
    const float* nb = g_net + (size_t)b * TT * HH;
#pragma unroll
    for (int k = 0; k < KK; ++k) {
        float wk = __shfl_sync(0xffffffffu, e, k) * inv;
        int   jk = __shfl_sync(0xffffffffu, j, k);
        float4 v = *(const float4*)(nb + (size_t)jk * HH + lane * 4);
        acc.x = fmaf(wk, v.x, acc.x);
        acc.y = fmaf(wk, v.y, acc.y);
        acc.z = fmaf(wk, v.z, acc.z);
        acc.w = fmaf(wk, v.w, acc.w);
    }
    *(float4*)(g_att + (size_t)t * HH + lane * 4) = acc;
}

// ======================= weight prep ====================================
// 48 K16-chunk slots per block:
//   Wo: 0..7, W0: 8..23 (K=256), W1: 24..31, Ws: 32..47 (K=256)
__global__ __launch_bounds__(256) void prep_weights(
    const float* __restrict__ Wo, const float* __restrict__ W0,
    const float* __restrict__ W1, const float* __restrict__ Ws, int base)
{
    const int blk = blockIdx.y;
    const int slot = blockIdx.x + base;
    const float* W; int ck;
    if (slot < 8)       { W = Wo + (size_t)blk*128*128; ck = slot; }
    else if (slot < 24) { W = W0 + (size_t)blk*256*128; ck = slot-8; }
    else if (slot < 32) { W = W1 + (size_t)blk*128*128; ck = slot-24; }
    else                { W = Ws + (size_t)blk*256*128; ck = slot-32; }
    float* img = g_bprep + ((size_t)blk*48 + slot)*4096;

    for (int idx = threadIdx.x; idx < 2048; idx += 256) {
        int kk = idx >> 7, n = idx & 127;
        float v = W[(size_t)(ck*16 + kk)*128 + n];
        uint32_t h = tf32_hi(v);
        float hv = __uint_as_float(h);
        uint32_t l = tf32_hi(v - hv);
        img[idx]        = hv;
        img[2048 + idx] = __uint_as_float(l);
    }
}

// ======================= tensor-core resnet =============================
__device__ __forceinline__ void init_acc(float acc[2][8][4],
                                         const float* __restrict__ bias,
                                         int nb, int tig)
{
#pragma unroll
    for (int j = 0; j < 8; ++j) {
        int col0 = nb + j*8 + 2*tig;
        float b0v = __ldg(bias + col0);
        float b1v = __ldg(bias + col0 + 1);
#pragma unroll
        for (int mt = 0; mt < 2; ++mt) {
            acc[mt][j][0] = b0v; acc[mt][j][1] = b1v;
            acc[mt][j][2] = b0v; acc[mt][j][3] = b1v;
        }
    }
}

template<bool RELU>
__device__ __forceinline__ void gemm_tc(
    const float* As, const float* __restrict__ prep, int nchunks,
    float acc[2][8][4], float* Bs, int tid, int rb, int nb)
{
    const int lane = tid & 31;
    const int gid = lane >> 2, tig = lane & 3;

    for (int c = 0; c < nchunks; ++c) {
        __syncthreads();
        const float* src = prep + (size_t)c * 4096;
#pragma unroll
        for (int i = 0; i < 2; ++i) {
            int idx4 = tid + i*256;                  // < 512
            int kk = idx4 >> 5, n4 = (idx4 & 31) << 2;
            *(float4*)(Bs + kk*BSTR + n4)             = *(const float4*)(src + idx4*4);
            *(float4*)(Bs + 16*BSTR + kk*BSTR + n4)   = *(const float4*)(src + 2048 + idx4*4);
        }
        __syncthreads();

#pragma unroll
        for (int ks = 0; ks < 2; ++ks) {
            const int k0 = c*16 + ks*8;
            uint32_t Ah[2][4], Al[2][4];
#pragma unroll
            for (int mt = 0; mt < 2; ++mt) {
                const int r0 = rb + mt*16 + gid;
                float f[4];
                f[0] = As[(size_t)r0*SX + k0 + tig];
                f[1] = As[(size_t)(r0+8)*SX + k0 + tig];
                f[2] = As[(size_t)r0*SX + k0 + tig + 4];
                f[3] = As[(size_t)(r0+8)*SX + k0 + tig + 4];
#pragma unroll
                for (int i = 0; i < 4; ++i) {
                    float v = RELU ? fmaxf(f[i], 0.0f) : f[i];
                    uint32_t h = tf32_hi(v);
                    Ah[mt][i] = h;
                    Al[mt][i] = tf32_hi(v - __uint_as_float(h));
                }
            }
#pragma unroll
            for (int j = 0; j < 8; ++j) {
                const int nbase = nb + j*8 + gid;
                const float* bk0 = Bs + (ks*8 + tig)*BSTR + nbase;
                const float* bk1 = Bs + (ks*8 + tig + 4)*BSTR + nbase;
                uint32_t bh[2], bl[2];
                bh[0] = __float_as_uint(bk0[0]);
                bh[1] = __float_as_uint(bk1[0]);
                bl[0] = __float_as_uint(bk0[16*BSTR]);
                bl[1] = __float_as_uint(bk1[16*BSTR]);
#pragma unroll
                for (int mt = 0; mt < 2; ++mt) {
                    MMA_TF32(acc[mt][j], Ah[mt], bh);
                    MMA_TF32(acc[mt][j], Al[mt], bh);
                    MMA_TF32(acc[mt][j], Ah[mt], bl);
                }
            }
        }
    }
}

template<bool RELU>
__device__ __forceinline__ void store_acc_smem(float acc[2][8][4], float* tile,
                                               int rb, int nb, int lane)
{
    const int gid = lane >> 2, tig = lane & 3;
#pragma unroll
    for (int mt = 0; mt < 2; ++mt) {
        const int rg = rb + mt*16 + gid;
#pragma unroll
        for (int j = 0; j < 8; ++j) {
            const int col0 = nb + j*8 + 2*tig;
            float v0 = acc[mt][j][0], v1 = acc[mt][j][1];
            float v2 = acc[mt][j][2], v3 = acc[mt][j][3];
            if (RELU) {
                v0 = fmaxf(v0, 0.f); v1 = fmaxf(v1, 0.f);
                v2 = fmaxf(v2, 0.f); v3 = fmaxf(v3, 0.f);
            }
            *(float2*)(tile + (size_t)rg*SX + col0)     = make_float2(v0, v1);
            *(float2*)(tile + (size_t)(rg+8)*SX + col0) = make_float2(v2, v3);
        }
    }
}

__global__ __launch_bounds__(256) void resnet_tc(
    int blk,
    const float* __restrict__ b0, const float* __restrict__ b1,
    const float* __restrict__ bo, int add_res)
{
    extern __shared__ float sm[];
    float* xs  = sm;                 // [128][SX] net (x)
    float* as_ = sm + 128*SX;        // [128][SX] a1
    float* hs  = sm + 2*128*SX;      // [128][SX] att, then relu(h)
    float* Bs  = sm + 3*128*SX;      // [32][BSTR] hi+lo chunk

    const int tid = threadIdx.x;
    const int wid = tid >> 5, lane = tid & 31;
    const int rb = (wid & 3) * 32;
    const int nb = (wid >> 2) * 64;
    const int gid = lane >> 2, tig = lane & 3;
    const size_t t0 = (size_t)blockIdx.x * 128;
    const float* prep = g_bprep + (size_t)blk * 48 * 4096;

    for (int q = tid; q < 128 * 32; q += 256) {
        int r = q >> 5, c = (q & 31) << 2;
        *(float4*)(xs + r * SX + c) = *(const float4*)(g_net + (t0 + r) * HH + c);
        *(float4*)(hs + r * SX + c) = *(const float4*)(g_att + (t0 + r) * HH + c);
    }

    float acc[2][8][4];

    // ---- GEMM1: a1 = att @ Wo^T + bo -> as_
    init_acc(acc, bo, nb, tig);
    gemm_tc<false>(hs, prep + 0*4096, 8, acc, Bs, tid, rb, nb);
    store_acc_smem<false>(acc, as_, rb, nb, lane);

    // ---- GEMM2: h = relu(relu([x|a1]) @ W0 + b0) -> hs
    init_acc(acc, b0, nb, tig);
    gemm_tc<true>(xs,  prep + 8*4096,  8, acc, Bs, tid, rb, nb);
    gemm_tc<true>(as_, prep + 16*4096, 8, acc, Bs, tid, rb, nb);
    __syncthreads();
    store_acc_smem<true>(acc, hs, rb, nb, lane);

    // ---- GEMM3+4: out = h @ W1^T + b1 + [x|a1] @ Ws^T [+ residual x]
    init_acc(acc, b1, nb, tig);
    gemm_tc<false>(hs,  prep + 24*4096, 8, acc, Bs, tid, rb, nb);
    gemm_tc<false>(xs,  prep + 32*4096, 8, acc, Bs, tid, rb, nb);
    gemm_tc<false>(as_, prep + 40*4096, 8, acc, Bs, tid, rb, nb);

#pragma unroll
    for (int mt = 0; mt < 2; ++mt) {
        const int rg = rb + mt*16 + gid;
#pragma unroll
        for (int j = 0; j < 8; ++j) {
            const int col0 = nb + j*8 + 2*tig;
            float v0 = acc[mt][j][0], v1 = acc[mt][j][1];
            float v2 = acc[mt][j][2], v3 = acc[mt][j][3];
            if (add_res) {
                float2 r0 = *(const float2*)(xs + (size_t)rg*SX + col0);
                float2 r1 = *(const float2*)(xs + (size_t)(rg+8)*SX + col0);
                v0 += r0.x; v1 += r0.y; v2 += r1.x; v3 += r1.y;
            }
            *(float2*)(g_net + (t0 + rg) * HH + col0)     = make_float2(v0, v1);
            *(float2*)(g_net + (t0 + rg + 8) * HH + col0) = make_float2(v2, v3);
        }
    }
}

// ======================= final projection (scalar, FFMA2) ===============
__device__ __forceinline__ void init_bias_f(u64 acc[8][4], const float* __restrict__ bias, int nb)
{
    ulonglong2 q0 = *(const ulonglong2*)(bias + nb);
    ulonglong2 q1 = *(const ulonglong2*)(bias + nb + 4);
#pragma unroll
    for (int r = 0; r < 8; ++r) {
        acc[r][0] = q0.x; acc[r][1] = q0.y; acc[r][2] = q1.x; acc[r][3] = q1.y;
    }
}

__global__ __launch_bounds__(256) void final_kernel(const float* __restrict__ W_c,
                                                    const float* __restrict__ b_c,
                                                    float* __restrict__ out)
{
    extern __shared__ float sm[];
    float* xs = sm;              // [128][SX]
    float* ws = sm + 128 * SX;   // [32][128]

    const int tid = threadIdx.x;
    const int tx = tid & 15;
    const int ty = tid >> 4;
    const int nb = tx * 8;
    const int rb = ty * 8;
    const size_t t0 = (size_t)blockIdx.x * 128;

    for (int q = tid; q < 128 * 32; q += 256) {
        int r = q >> 5, c = (q & 31) << 2;
        *(float4*)(xs + r * SX + c) = *(const float4*)(g_net + (t0 + r) * HH + c);
    }

    u64 acc[8][4];
    init_bias_f(acc, b_c, nb);

    for (int kt = 0; kt < 128; kt += 32) {
        __syncthreads();
        for (int q = tid; q < 1024; q += 256) {
            int kk = q >> 5, c = (q & 31) << 2;
            *(float4*)(ws + kk * 128 + c) = *(const float4*)(W_c + (size_t)(kt + kk) * 128 + c);
        }
        __syncthreads();
#pragma unroll 1
        for (int k4 = 0; k4 < 8; ++k4) {
            float4 a4[8];
#pragma unroll
            for (int r = 0; r < 8; ++r)
                a4[r] = *(const float4*)(xs + (rb + r) * SX + kt + k4 * 4);
#pragma unroll
            for (int j = 0; j < 4; ++j) {
                int kk = k4 * 4 + j;
                ulonglong2 b0v = *(const ulonglong2*)(ws + kk * 128 + nb);
                ulonglong2 b1v = *(const ulonglong2*)(ws + kk * 128 + nb + 4);
#pragma unroll
                for (int r = 0; r < 8; ++r) {
                    float a = ((const float*)&a4[r])[j];
                    u64 aa; BCAST2(aa, __float_as_uint(a));
                    FMA2(acc[r][0], aa, b0v.x, acc[r][0]);
                    FMA2(acc[r][1], aa, b0v.y, acc[r][1]);
                    FMA2(acc[r][2], aa, b1v.x, acc[r][2]);
                    FMA2(acc[r][3], aa, b1v.y, acc[r][3]);
                }
            }
        }
    }
#pragma unroll
    for (int r = 0; r < 8; ++r) {
        *(ulonglong2*)(out + (t0 + rb + r) * HH + nb)     = make_ulonglong2(acc[r][0], acc[r][1]);
        *(ulonglong2*)(out + (t0 + rb + r) * HH + nb + 4) = make_ulonglong2(acc[r][2], acc[r][3]);
    }
}

// ======================= launch =========================================
extern "C" void kernel_launch(void* const* d_in, const int* in_sizes, int n_in,
                              void* d_out, int out_size)
{
    const float* p      = (const float*)d_in[0];
    const float* W_pos  = (const float*)d_in[1];
    const float* b_pos  = (const float*)d_in[2];
    const float* blk_W0 = (const float*)d_in[3];
    const float* blk_b0 = (const float*)d_in[4];
    const float* blk_W1 = (const float*)d_in[5];
    const float* blk_b1 = (const float*)d_in[6];
    const float* blk_Ws = (const float*)d_in[7];
    const float* att_Wc = (const float*)d_in[8];
    const float* att_bc = (const float*)d_in[9];
    const float* att_Wo = (const float*)d_in[10];
    const float* att_bo = (const float*)d_in[11];
    const float* W_c    = (const float*)d_in[12];
    const float* b_c    = (const float*)d_in[13];
    float* out = (float*)d_out;

    const int RES_SMEM = (3 * 128 * SX + 32 * BSTR) * 4;   // 220,160 B
    const int FIN_SMEM = (128 * SX + 32 * 128) * 4;        //  83,968 B
    cudaFuncSetAttribute(resnet_tc,   cudaFuncAttributeMaxDynamicSharedMemorySize, RES_SMEM);
    cudaFuncSetAttribute(final_kernel, cudaFuncAttributeMaxDynamicSharedMemorySize, FIN_SMEM);

    // launch order: 0=prep0, 1=prep1, 2=knn, 3=pos, 4=attn0, 5=resnet0
    // so ncu (-s 5 -c 1) captures resnet_tc.
    prep_weights<<<dim3(24, NBLK), 256>>>(att_Wo, blk_W0, blk_W1, blk_Ws, 0);
    prep_weights<<<dim3(24, NBLK), 256>>>(att_Wo, blk_W0, blk_W1, blk_Ws, 24);
    knn_kernel<<<dim3(TT / 128, BB), 128>>>(p);
    pos_kernel<<<(BT * HH) / 256, 256>>>(p, W_pos, b_pos);

    for (int i = 0; i < NBLK; ++i) {
        attn_kernel<<<BT / 8, 256>>>(p, att_Wc + (size_t)i * 7, att_bc + i);
        resnet_tc<<<BT / 128, 256, RES_SMEM>>>(
            i, blk_b0 + (size_t)i * 128, blk_b1 + (size_t)i * 128,
            att_bo + (size_t)i * 128, i > 0 ? 1 : 0);
    }
    final_kernel<<<BT / 128, 256, FIN_SMEM>>>(W_c, b_c, out);
}

// round 9
// speedup vs baseline: 1.9761x; 1.1898x over previous
#include <cuda_runtime.h>
#include <cuda_bf16.h>
#include <math.h>
#include <float.h>
#include <stdint.h>

#define BB 8
#define TT 4096
#define HH 128
#define NBLK 6
#define KK 20
#define BT (BB*TT)   // 32768
#define SX 132       // activation tile stride (floats)

typedef unsigned long long u64;

// packed f32x2 helpers (scalar kernels)
#define FMA2(d, a, b, c) \
    asm("fma.rn.f32x2 %0, %1, %2, %3;" : "=l"(d) : "l"(a), "l"(b), "l"(c))
#define BCAST2(d, s) \
    asm("mov.b64 %0, {%1, %1};" : "=l"(d) : "r"(s))

// bf16 mma (sm_80+ PTX, valid at target sm_103)
#define MMA_BF16(d, a, b) \
    asm volatile("mma.sync.aligned.m16n8k16.row.col.f32.bf16.bf16.f32 " \
        "{%0,%1,%2,%3}, {%4,%5,%6,%7}, {%8,%9}, {%0,%1,%2,%3};" \
        : "+f"((d)[0]), "+f"((d)[1]), "+f"((d)[2]), "+f"((d)[3]) \
        : "r"((a)[0]), "r"((a)[1]), "r"((a)[2]), "r"((a)[3]), \
          "r"((b)[0]), "r"((b)[1]))

// pack two f32 into bf16x2: low 16 bits <- vlo, high <- vhi
__device__ __forceinline__ uint32_t pack_bf16x2(float vlo, float vhi) {
    uint32_t r;
    asm("cvt.rn.bf16x2.f32 %0, %1, %2;" : "=r"(r) : "f"(vhi), "f"(vlo));
    return r;
}

// ---------------- scratch (device globals; no allocation) ----------------
__device__ float g_net[BT * HH];   // 16 MB
__device__ float g_att[BT * HH];   // 16 MB
__device__ int   g_idx[BT * KK];
__device__ float g_dis[BT * KK];
// prepped weights: per block 48 K16-chunks x (hi 1024 + lo 1024 words bf16x2)
__device__ float g_bprep[NBLK * 48 * 2048];   // 2.4 MB

// ======================= KNN (scalar, proven) ===========================
__global__ __launch_bounds__(128) void knn_kernel(const float* __restrict__ p)
{
    const int b  = blockIdx.y;
    const int tt = blockIdx.x * 128 + threadIdx.x;
    const float* pb = p + (size_t)b * TT * 3;

    const float qx = pb[tt*3 + 0];
    const float qy = pb[tt*3 + 1];
    const float qz = pb[tt*3 + 2];
    const float sqq = (qx*qx + qy*qy) + qz*qz;

    float bd[KK];
    int   bi[KK];
#pragma unroll
    for (int k = 0; k < KK; ++k) { bd[k] = FLT_MAX; bi[k] = 0; }

    __shared__ float4 sp[1024];   // x,y,z,|.|^2

    for (int s0 = 0; s0 < TT; s0 += 1024) {
        __syncthreads();
        for (int l = threadIdx.x; l < 1024; l += 128) {
            const float* q = pb + (size_t)(s0 + l) * 3;
            float x = q[0], y = q[1], z = q[2];
            sp[l] = make_float4(x, y, z, (x*x + y*y) + z*z);
        }
        __syncthreads();
#pragma unroll 4
        for (int l = 0; l < 1024; ++l) {
            float4 v = sp[l];
            float dot = qx*v.x + qy*v.y + qz*v.z;
            float d2  = sqq + v.w - 2.0f * dot;
            if (d2 < bd[KK-1]) {
                bd[KK-1] = d2; bi[KK-1] = s0 + l;
#pragma unroll
                for (int q2 = KK-1; q2 > 0; --q2) {
                    if (bd[q2] < bd[q2-1]) {
                        float td = bd[q2]; bd[q2] = bd[q2-1]; bd[q2-1] = td;
                        int   ti = bi[q2]; bi[q2] = bi[q2-1]; bi[q2-1] = ti;
                    }
                }
            }
        }
    }

    const size_t o = ((size_t)b * TT + tt) * KK;
#pragma unroll
    for (int k = 0; k < KK; ++k) {
        g_idx[o + k] = bi[k];
        g_dis[o + k] = sqrtf(fmaxf(bd[k], 1e-12f));
    }
}

// ======================= positional encoding ============================
__global__ __launch_bounds__(256) void pos_kernel(const float* __restrict__ p,
                                                  const float* __restrict__ W_pos,
                                                  const float* __restrict__ b_pos)
{
    int gid = blockIdx.x * 256 + threadIdx.x;
    int t = gid >> 7;
    int h = gid & 127;
    const float* pp = p + (size_t)t * 3;
    float v = b_pos[h];
    v = fmaf(pp[0], W_pos[h],        v);
    v = fmaf(pp[1], W_pos[HH + h],   v);
    v = fmaf(pp[2], W_pos[2*HH + h], v);
    g_net[gid] = v;
}

// ======================= attention (gather + softmax) ===================
__global__ __launch_bounds__(256) void attn_kernel(const float* __restrict__ p,
                                                   const float* __restrict__ wc,
                                                   const float* __restrict__ bc)
{
    const int warp = threadIdx.x >> 5;
    const int lane = threadIdx.x & 31;
    const int t  = blockIdx.x * 8 + warp;
    const int b  = t >> 12;
    const int tt = t & (TT - 1);
    const float* pb = p + (size_t)b * TT * 3;

    const float q0 = pb[tt*3+0], q1 = pb[tt*3+1], q2 = pb[tt*3+2];
    const float w0 = wc[0], w1 = wc[1], w2 = wc[2], w3 = wc[3];
    const float w4 = wc[4], w5 = wc[5], w6 = wc[6], bcv = bc[0];

    float s = -FLT_MAX;
    int   j = 0;
    if (lane < KK) {
        size_t o = (size_t)t * KK + lane;
        j = g_idx[o];
        float d = g_dis[o];
        const float* px = pb + (size_t)j * 3;
        s = bcv;
        s = fmaf(w0, d,     s);
        s = fmaf(w1, px[0], s);
        s = fmaf(w2, px[1], s);
        s = fmaf(w3, px[2], s);
        s = fmaf(w4, q0,    s);
        s = fmaf(w5, q1,    s);
        s = fmaf(w6, q2,    s);
    }
    float m = s;
#pragma unroll
    for (int off = 16; off; off >>= 1)
        m = fmaxf(m, __shfl_xor_sync(0xffffffffu, m, off));
    float e = (lane < KK) ? expf(s - m) : 0.0f;
    float sum = e;
#pragma unroll
    for (int off = 16; off; off >>= 1)
        sum += __shfl_xor_sync(0xffffffffu, sum, off);
    const float inv = 1.0f / sum;

    float4 acc = make_float4(0.f, 0.f, 0.f, 0.f);
    const float* nb = g_net + (size_t)b * TT * HH;
#pragma unroll
    for (int k = 0; k < KK; ++k) {
        float wk = __shfl_sync(0xffffffffu, e, k) * inv;
        int   jk = __shfl_sync(0xffffffffu, j, k);
        float4 v = *(const float4*)(nb + (size_t)jk * HH + lane * 4);
        acc.x = fmaf(wk, v.x, acc.x);
        acc.y = fmaf(wk, v.y, acc.y);
        acc.z = fmaf(wk, v.z, acc.z);
        acc.w = fmaf(wk, v.w, acc.w);
    }
    *(float4*)(g_att + (size_t)t * HH + lane * 4) = acc;
}

// ======================= weight prep (bf16 hi/lo) =======================
// 48 K16-chunk slots per block: Wo 0..7, W0 8..23, W1 24..31, Ws 32..47.
// Chunk image (2048 words): hi[kpair 0..7][n 0..127] then lo[8][128].
// Word = bf16x2 of (W[2kp][n], W[2kp+1][n]) — low half = even k.
__global__ __launch_bounds__(256) void prep_weights(
    const float* __restrict__ Wo, const float* __restrict__ W0,
    const float* __restrict__ W1, const float* __restrict__ Ws)
{
    const int blk = blockIdx.y;
    const int slot = blockIdx.x;
    const float* W; int ck;
    if (slot < 8)       { W = Wo + (size_t)blk*128*128; ck = slot; }
    else if (slot < 24) { W = W0 + (size_t)blk*256*128; ck = slot-8; }
    else if (slot < 32) { W = W1 + (size_t)blk*128*128; ck = slot-24; }
    else                { W = Ws + (size_t)blk*256*128; ck = slot-32; }
    float* img = g_bprep + ((size_t)blk*48 + slot)*2048;

    for (int idx = threadIdx.x; idx < 1024; idx += 256) {
        int kp = idx >> 7, n = idx & 127;
        float w0 = W[(size_t)(ck*16 + 2*kp    )*128 + n];
        float w1 = W[(size_t)(ck*16 + 2*kp + 1)*128 + n];
        uint32_t h = pack_bf16x2(w0, w1);
        float h0 = __uint_as_float(h << 16);
        float h1 = __uint_as_float(h & 0xffff0000u);
        uint32_t l = pack_bf16x2(w0 - h0, w1 - h1);
        img[idx]        = __uint_as_float(h);
        img[1024 + idx] = __uint_as_float(l);
    }
}

// ======================= tensor-core resnet (bf16 3-pass) ================
__device__ __forceinline__ void init_acc(float acc[2][8][4],
                                         const float* __restrict__ bias,
                                         int nb, int tig)
{
#pragma unroll
    for (int j = 0; j < 8; ++j) {
        int col0 = nb + j*8 + 2*tig;
        float b0v = __ldg(bias + col0);
        float b1v = __ldg(bias + col0 + 1);
#pragma unroll
        for (int mt = 0; mt < 2; ++mt) {
            acc[mt][j][0] = b0v; acc[mt][j][1] = b1v;
            acc[mt][j][2] = b0v; acc[mt][j][3] = b1v;
        }
    }
}

// Bs layout: hi [8 kpairs][132 words], lo at offset 1056.
#define BLO 1056

template<bool RELU>
__device__ __forceinline__ void gemm_tc(
    const float* As, const float* __restrict__ prep, int nchunks,
    float acc[2][8][4], float* Bs, int tid, int rb, int nb)
{
    const int lane = tid & 31;
    const int gid = lane >> 2, tig = lane & 3;
    const int srow = tid >> 5, scol4 = (tid & 31) << 2;

    for (int c = 0; c < nchunks; ++c) {
        __syncthreads();
        const float* src = prep + (size_t)c * 2048;
        *(float4*)(Bs + srow*132 + scol4)       = *(const float4*)(src + tid*4);
        *(float4*)(Bs + BLO + srow*132 + scol4) = *(const float4*)(src + 1024 + tid*4);
        __syncthreads();

        const int k0 = c*16;
        uint32_t Ah[2][4], Al[2][4];
#pragma unroll
        for (int mt = 0; mt < 2; ++mt) {
            const float* ap = As + (size_t)(rb + mt*16 + gid)*SX + k0 + 2*tig;
            float2 f[4];
            f[0] = *(const float2*)(ap);
            f[1] = *(const float2*)(ap + 8*SX);
            f[2] = *(const float2*)(ap + 8);
            f[3] = *(const float2*)(ap + 8*SX + 8);
#pragma unroll
            for (int i = 0; i < 4; ++i) {
                float x = f[i].x, y = f[i].y;
                if (RELU) { x = fmaxf(x, 0.f); y = fmaxf(y, 0.f); }
                uint32_t h = pack_bf16x2(x, y);
                float h0 = __uint_as_float(h << 16);
                float h1 = __uint_as_float(h & 0xffff0000u);
                Ah[mt][i] = h;
                Al[mt][i] = pack_bf16x2(x - h0, y - h1);
            }
        }
#pragma unroll
        for (int j = 0; j < 8; ++j) {
            const int n = nb + j*8 + gid;
            uint32_t bh[2], bl[2];
            bh[0] = __float_as_uint(Bs[tig*132 + n]);
            bh[1] = __float_as_uint(Bs[(tig+4)*132 + n]);
            bl[0] = __float_as_uint(Bs[BLO + tig*132 + n]);
            bl[1] = __float_as_uint(Bs[BLO + (tig+4)*132 + n]);
#pragma unroll
            for (int mt = 0; mt < 2; ++mt) {
                MMA_BF16(acc[mt][j], Ah[mt], bh);
                MMA_BF16(acc[mt][j], Al[mt], bh);
                MMA_BF16(acc[mt][j], Ah[mt], bl);
            }
        }
    }
}

template<bool RELU>
__device__ __forceinline__ void store_acc_smem(float acc[2][8][4], float* tile,
                                               int rb, int nb, int lane)
{
    const int gid = lane >> 2, tig = lane & 3;
#pragma unroll
    for (int mt = 0; mt < 2; ++mt) {
        const int rg = rb + mt*16 + gid;
#pragma unroll
        for (int j = 0; j < 8; ++j) {
            const int col0 = nb + j*8 + 2*tig;
            float v0 = acc[mt][j][0], v1 = acc[mt][j][1];
            float v2 = acc[mt][j][2], v3 = acc[mt][j][3];
            if (RELU) {
                v0 = fmaxf(v0, 0.f); v1 = fmaxf(v1, 0.f);
                v2 = fmaxf(v2, 0.f); v3 = fmaxf(v3, 0.f);
            }
            *(float2*)(tile + (size_t)rg*SX + col0)     = make_float2(v0, v1);
            *(float2*)(tile + (size_t)(rg+8)*SX + col0) = make_float2(v2, v3);
        }
    }
}

__global__ __launch_bounds__(256) void resnet_tc(
    int blk,
    const float* __restrict__ b0, const float* __restrict__ b1,
    const float* __restrict__ bo, int add_res)
{
    extern __shared__ float sm[];
    float* xs  = sm;                 // [128][SX] net (x)
    float* as_ = sm + 128*SX;        // [128][SX] a1
    float* hs  = sm + 2*128*SX;      // [128][SX] att, then relu(h)
    float* Bs  = sm + 3*128*SX;      // hi[8][132] + lo[8][132]

    const int tid = threadIdx.x;
    const int wid = tid >> 5, lane = tid & 31;
    const int rb = (wid & 3) * 32;
    const int nb = (wid >> 2) * 64;
    const int gid = lane >> 2, tig = lane & 3;
    const size_t t0 = (size_t)blockIdx.x * 128;
    const float* prep = g_bprep + (size_t)blk * 48 * 2048;

    for (int q = tid; q < 128 * 32; q += 256) {
        int r = q >> 5, c = (q & 31) << 2;
        *(float4*)(xs + r * SX + c) = *(const float4*)(g_net + (t0 + r) * HH + c);
        *(float4*)(hs + r * SX + c) = *(const float4*)(g_att + (t0 + r) * HH + c);
    }

    float acc[2][8][4];

    // ---- GEMM1: a1 = att @ Wo^T + bo -> as_
    init_acc(acc, bo, nb, tig);
    gemm_tc<false>(hs, prep + 0*2048, 8, acc, Bs, tid, rb, nb);
    store_acc_smem<false>(acc, as_, rb, nb, lane);

    // ---- GEMM2: h = relu(relu([x|a1]) @ W0 + b0) -> hs
    init_acc(acc, b0, nb, tig);
    gemm_tc<true>(xs,  prep + 8*2048,  8, acc, Bs, tid, rb, nb);
    gemm_tc<true>(as_, prep + 16*2048, 8, acc, Bs, tid, rb, nb);
    __syncthreads();
    store_acc_smem<true>(acc, hs, rb, nb, lane);

    // ---- GEMM3+4: out = h @ W1^T + b1 + [x|a1] @ Ws^T [+ residual x]
    init_acc(acc, b1, nb, tig);
    gemm_tc<false>(hs,  prep + 24*2048, 8, acc, Bs, tid, rb, nb);
    gemm_tc<false>(xs,  prep + 32*2048, 8, acc, Bs, tid, rb, nb);
    gemm_tc<false>(as_, prep + 40*2048, 8, acc, Bs, tid, rb, nb);

#pragma unroll
    for (int mt = 0; mt < 2; ++mt) {
        const int rg = rb + mt*16 + gid;
#pragma unroll
        for (int j = 0; j < 8; ++j) {
            const int col0 = nb + j*8 + 2*tig;
            float v0 = acc[mt][j][0], v1 = acc[mt][j][1];
            float v2 = acc[mt][j][2], v3 = acc[mt][j][3];
            if (add_res) {
                float2 r0 = *(const float2*)(xs + (size_t)rg*SX + col0);
                float2 r1 = *(const float2*)(xs + (size_t)(rg+8)*SX + col0);
                v0 += r0.x; v1 += r0.y; v2 += r1.x; v3 += r1.y;
            }
            *(float2*)(g_net + (t0 + rg) * HH + col0)     = make_float2(v0, v1);
            *(float2*)(g_net + (t0 + rg + 8) * HH + col0) = make_float2(v2, v3);
        }
    }
}

// ======================= final projection (scalar, FFMA2) ===============
__device__ __forceinline__ void init_bias_f(u64 acc[8][4], const float* __restrict__ bias, int nb)
{
    ulonglong2 q0 = *(const ulonglong2*)(bias + nb);
    ulonglong2 q1 = *(const ulonglong2*)(bias + nb + 4);
#pragma unroll
    for (int r = 0; r < 8; ++r) {
        acc[r][0] = q0.x; acc[r][1] = q0.y; acc[r][2] = q1.x; acc[r][3] = q1.y;
    }
}

__global__ __launch_bounds__(256) void final_kernel(const float* __restrict__ W_c,
                                                    const float* __restrict__ b_c,
                                                    float* __restrict__ out)
{
    extern __shared__ float sm[];
    float* xs = sm;              // [128][SX]
    float* ws = sm + 128 * SX;   // [32][128]

    const int tid = threadIdx.x;
    const int tx = tid & 15;
    const int ty = tid >> 4;
    const int nb = tx * 8;
    const int rb = ty * 8;
    const size_t t0 = (size_t)blockIdx.x * 128;

    for (int q = tid; q < 128 * 32; q += 256) {
        int r = q >> 5, c = (q & 31) << 2;
        *(float4*)(xs + r * SX + c) = *(const float4*)(g_net + (t0 + r) * HH + c);
    }

    u64 acc[8][4];
    init_bias_f(acc, b_c, nb);

    for (int kt = 0; kt < 128; kt += 32) {
        __syncthreads();
        for (int q = tid; q < 1024; q += 256) {
            int kk = q >> 5, c = (q & 31) << 2;
            *(float4*)(ws + kk * 128 + c) = *(const float4*)(W_c + (size_t)(kt + kk) * 128 + c);
        }
        __syncthreads();
#pragma unroll 1
        for (int k4 = 0; k4 < 8; ++k4) {
            float4 a4[8];
#pragma unroll
            for (int r = 0; r < 8; ++r)
                a4[r] = *(const float4*)(xs + (rb + r) * SX + kt + k4 * 4);
#pragma unroll
            for (int j = 0; j < 4; ++j) {
                int kk = k4 * 4 + j;
                ulonglong2 b0v = *(const ulonglong2*)(ws + kk * 128 + nb);
                ulonglong2 b1v = *(const ulonglong2*)(ws + kk * 128 + nb + 4);
#pragma unroll
                for (int r = 0; r < 8; ++r) {
                    float a = ((const float*)&a4[r])[j];
                    u64 aa; BCAST2(aa, __float_as_uint(a));
                    FMA2(acc[r][0], aa, b0v.x, acc[r][0]);
                    FMA2(acc[r][1], aa, b0v.y, acc[r][1]);
                    FMA2(acc[r][2], aa, b1v.x, acc[r][2]);
                    FMA2(acc[r][3], aa, b1v.y, acc[r][3]);
                }
            }
        }
    }
#pragma unroll
    for (int r = 0; r < 8; ++r) {
        *(ulonglong2*)(out + (t0 + rb + r) * HH + nb)     = make_ulonglong2(acc[r][0], acc[r][1]);
        *(ulonglong2*)(out + (t0 + rb + r) * HH + nb + 4) = make_ulonglong2(acc[r][2], acc[r][3]);
    }
}

// ======================= launch =========================================
extern "C" void kernel_launch(void* const* d_in, const int* in_sizes, int n_in,
                              void* d_out, int out_size)
{
    const float* p      = (const float*)d_in[0];
    const float* W_pos  = (const float*)d_in[1];
    const float* b_pos  = (const float*)d_in[2];
    const float* blk_W0 = (const float*)d_in[3];
    const float* blk_b0 = (const float*)d_in[4];
    const float* blk_W1 = (const float*)d_in[5];
    const float* blk_b1 = (const float*)d_in[6];
    const float* blk_Ws = (const float*)d_in[7];
    const float* att_Wc = (const float*)d_in[8];
    const float* att_bc = (const float*)d_in[9];
    const float* att_Wo = (const float*)d_in[10];
    const float* att_bo = (const float*)d_in[11];
    const float* W_c    = (const float*)d_in[12];
    const float* b_c    = (const float*)d_in[13];
    float* out = (float*)d_out;

    const int RES_SMEM = (3 * 128 * SX + 2 * 8 * 132) * 4;   // 211,200 B
    const int FIN_SMEM = (128 * SX + 32 * 128) * 4;          //  83,968 B
    cudaFuncSetAttribute(resnet_tc,   cudaFuncAttributeMaxDynamicSharedMemorySize, RES_SMEM);
    cudaFuncSetAttribute(final_kernel, cudaFuncAttributeMaxDynamicSharedMemorySize, FIN_SMEM);

    prep_weights<<<dim3(48, NBLK), 256>>>(att_Wo, blk_W0, blk_W1, blk_Ws);
    knn_kernel<<<dim3(TT / 128, BB), 128>>>(p);
    pos_kernel<<<(BT * HH) / 256, 256>>>(p, W_pos, b_pos);

    for (int i = 0; i < NBLK; ++i) {
        attn_kernel<<<BT / 8, 256>>>(p, att_Wc + (size_t)i * 7, att_bc + i);
        resnet_tc<<<BT / 128, 256, RES_SMEM>>>(
            i, blk_b0 + (size_t)i * 128, blk_b1 + (size_t)i * 128,
            att_bo + (size_t)i * 128, i > 0 ? 1 : 0);
    }
    final_kernel<<<BT / 128, 256, FIN_SMEM>>>(W_c, b_c, out);
}

// round 10
// speedup vs baseline: 2.0236x; 1.0241x over previous
#include <cuda_runtime.h>
#include <cuda_bf16.h>
#include <math.h>
#include <float.h>
#include <stdint.h>

#define BB 8
#define TT 4096
#define HH 128
#define NBLK 6
#define KK 20
#define BT (BB*TT)   // 32768
#define SX 132       // f32 tile stride (final_kernel only)
#define AST 68       // bf16x2 image row stride (words)
#define AIMG (128*AST)

typedef unsigned long long u64;

// packed f32x2 helpers (scalar kernels)
#define FMA2(d, a, b, c) \
    asm("fma.rn.f32x2 %0, %1, %2, %3;" : "=l"(d) : "l"(a), "l"(b), "l"(c))
#define BCAST2(d, s) \
    asm("mov.b64 %0, {%1, %1};" : "=l"(d) : "r"(s))

// bf16 mma (sm_80+ PTX, valid at target sm_103)
#define MMA_BF16(d, a, b) \
    asm volatile("mma.sync.aligned.m16n8k16.row.col.f32.bf16.bf16.f32 " \
        "{%0,%1,%2,%3}, {%4,%5,%6,%7}, {%8,%9}, {%0,%1,%2,%3};" \
        : "+f"((d)[0]), "+f"((d)[1]), "+f"((d)[2]), "+f"((d)[3]) \
        : "r"((a)[0]), "r"((a)[1]), "r"((a)[2]), "r"((a)[3]), \
          "r"((b)[0]), "r"((b)[1]))

// pack two f32 into bf16x2: low 16 bits <- vlo, high <- vhi
__device__ __forceinline__ uint32_t pack_bf16x2(float vlo, float vhi) {
    uint32_t r;
    asm("cvt.rn.bf16x2.f32 %0, %1, %2;" : "=r"(r) : "f"(vhi), "f"(vlo));
    return r;
}

// split f32 pair -> (hi word, lo word)
__device__ __forceinline__ void split2(float x, float y, uint32_t& wh, uint32_t& wl) {
    wh = pack_bf16x2(x, y);
    float h0 = __uint_as_float(wh << 16);
    float h1 = __uint_as_float(wh & 0xffff0000u);
    wl = pack_bf16x2(x - h0, y - h1);
}

// ---------------- scratch (device globals; no allocation) ----------------
__device__ float g_net[BT * HH];   // 16 MB
__device__ float g_att[BT * HH];   // 16 MB
__device__ int   g_idx[BT * KK];
__device__ float g_dis[BT * KK];
// prepped weights: per block 48 K16-chunks x (hi 1024 + lo 1024 words bf16x2)
__device__ float g_bprep[NBLK * 48 * 2048];   // 2.4 MB

// ======================= KNN (scalar, proven) ===========================
__global__ __launch_bounds__(128) void knn_kernel(const float* __restrict__ p)
{
    const int b  = blockIdx.y;
    const int tt = blockIdx.x * 128 + threadIdx.x;
    const float* pb = p + (size_t)b * TT * 3;

    const float qx = pb[tt*3 + 0];
    const float qy = pb[tt*3 + 1];
    const float qz = pb[tt*3 + 2];
    const float sqq = (qx*qx + qy*qy) + qz*qz;

    float bd[KK];
    int   bi[KK];
#pragma unroll
    for (int k = 0; k < KK; ++k) { bd[k] = FLT_MAX; bi[k] = 0; }

    __shared__ float4 sp[1024];   // x,y,z,|.|^2

    for (int s0 = 0; s0 < TT; s0 += 1024) {
        __syncthreads();
        for (int l = threadIdx.x; l < 1024; l += 128) {
            const float* q = pb + (size_t)(s0 + l) * 3;
            float x = q[0], y = q[1], z = q[2];
            sp[l] = make_float4(x, y, z, (x*x + y*y) + z*z);
        }
        __syncthreads();
#pragma unroll 4
        for (int l = 0; l < 1024; ++l) {
            float4 v = sp[l];
            float dot = qx*v.x + qy*v.y + qz*v.z;
            float d2  = sqq + v.w - 2.0f * dot;
            if (d2 < bd[KK-1]) {
                bd[KK-1] = d2; bi[KK-1] = s0 + l;
#pragma unroll
                for (int q2 = KK-1; q2 > 0; --q2) {
                    if (bd[q2] < bd[q2-1]) {
                        float td = bd[q2]; bd[q2] = bd[q2-1]; bd[q2-1] = td;
                        int   ti = bi[q2]; bi[q2] = bi[q2-1]; bi[q2-1] = ti;
                    }
                }
            }
        }
    }

    const size_t o = ((size_t)b * TT + tt) * KK;
#pragma unroll
    for (int k = 0; k < KK; ++k) {
        g_idx[o + k] = bi[k];
        g_dis[o + k] = sqrtf(fmaxf(bd[k], 1e-12f));
    }
}

// ======================= positional encoding ============================
__global__ __launch_bounds__(256) void pos_kernel(const float* __restrict__ p,
                                                  const float* __restrict__ W_pos,
                                                  const float* __restrict__ b_pos)
{
    int gid = blockIdx.x * 256 + threadIdx.x;
    int t = gid >> 7;
    int h = gid & 127;
    const float* pp = p + (size_t)t * 3;
    float v = b_pos[h];
    v = fmaf(pp[0], W_pos[h],        v);
    v = fmaf(pp[1], W_pos[HH + h],   v);
    v = fmaf(pp[2], W_pos[2*HH + h], v);
    g_net[gid] = v;
}

// ======================= attention (gather + softmax) ===================
__global__ __launch_bounds__(256) void attn_kernel(const float* __restrict__ p,
                                                   const float* __restrict__ wc,
                                                   const float* __restrict__ bc)
{
    const int warp = threadIdx.x >> 5;
    const int lane = threadIdx.x & 31;
    const int t  = blockIdx.x * 8 + warp;
    const int b  = t >> 12;
    const int tt = t & (TT - 1);
    const float* pb = p + (size_t)b * TT * 3;

    const float q0 = pb[tt*3+0], q1 = pb[tt*3+1], q2 = pb[tt*3+2];
    const float w0 = wc[0], w1 = wc[1], w2 = wc[2], w3 = wc[3];
    const float w4 = wc[4], w5 = wc[5], w6 = wc[6], bcv = bc[0];

    float s = -FLT_MAX;
    int   j = 0;
    if (lane < KK) {
        size_t o = (size_t)t * KK + lane;
        j = g_idx[o];
        float d = g_dis[o];
        const float* px = pb + (size_t)j * 3;
        s = bcv;
        s = fmaf(w0, d,     s);
        s = fmaf(w1, px[0], s);
        s = fmaf(w2, px[1], s);
        s = fmaf(w3, px[2], s);
        s = fmaf(w4, q0,    s);
        s = fmaf(w5, q1,    s);
        s = fmaf(w6, q2,    s);
    }
    float m = s;
#pragma unroll
    for (int off = 16; off; off >>= 1)
        m = fmaxf(m, __shfl_xor_sync(0xffffffffu, m, off));
    float e = (lane < KK) ? expf(s - m) : 0.0f;
    float sum = e;
#pragma unroll
    for (int off = 16; off; off >>= 1)
        sum += __shfl_xor_sync(0xffffffffu, sum, off);
    const float inv = 1.0f / sum;

    float4 acc = make_float4(0.f, 0.f, 0.f, 0.f);
    const float* nb = g_net + (size_t)b * TT * HH;
#pragma unroll
    for (int k = 0; k < KK; ++k) {
        float wk = __shfl_sync(0xffffffffu, e, k) * inv;
        int   jk = __shfl_sync(0xffffffffu, j, k);
        float4 v = *(const float4*)(nb + (size_t)jk * HH + lane * 4);
        acc.x = fmaf(wk, v.x, acc.x);
        acc.y = fmaf(wk, v.y, acc.y);
        acc.z = fmaf(wk, v.z, acc.z);
        acc.w = fmaf(wk, v.w, acc.w);
    }
    *(float4*)(g_att + (size_t)t * HH + lane * 4) = acc;
}

// ======================= weight prep (bf16 hi/lo) =======================
__global__ __launch_bounds__(256) void prep_weights(
    const float* __restrict__ Wo, const float* __restrict__ W0,
    const float* __restrict__ W1, const float* __restrict__ Ws)
{
    const int blk = blockIdx.y;
    const int slot = blockIdx.x;
    const float* W; int ck;
    if (slot < 8)       { W = Wo + (size_t)blk*128*128; ck = slot; }
    else if (slot < 24) { W = W0 + (size_t)blk*256*128; ck = slot-8; }
    else if (slot < 32) { W = W1 + (size_t)blk*128*128; ck = slot-24; }
    else                { W = Ws + (size_t)blk*256*128; ck = slot-32; }
    float* img = g_bprep + ((size_t)blk*48 + slot)*2048;

    for (int idx = threadIdx.x; idx < 1024; idx += 256) {
        int kp = idx >> 7, n = idx & 127;
        float w0 = W[(size_t)(ck*16 + 2*kp    )*128 + n];
        float w1 = W[(size_t)(ck*16 + 2*kp + 1)*128 + n];
        uint32_t h, l;
        split2(w0, w1, h, l);
        img[idx]        = __uint_as_float(h);
        img[1024 + idx] = __uint_as_float(l);
    }
}

// ======================= tensor-core resnet (bf16 tiles) =================
__device__ __forceinline__ void init_acc(float acc[2][8][4],
                                         const float* __restrict__ bias,
                                         int nb, int tig)
{
#pragma unroll
    for (int j = 0; j < 8; ++j) {
        int col0 = nb + j*8 + 2*tig;
        float b0v = __ldg(bias + col0);
        float b1v = __ldg(bias + col0 + 1);
#pragma unroll
        for (int mt = 0; mt < 2; ++mt) {
            acc[mt][j][0] = b0v; acc[mt][j][1] = b1v;
            acc[mt][j][2] = b0v; acc[mt][j][3] = b1v;
        }
    }
}

// zero both hi/lo halves of the split where the hi half is negative
__device__ __forceinline__ void relu_mask(uint32_t& ah, uint32_t& al)
{
    uint32_t t = ah & 0x80008000u;
    uint32_t m = t - (t >> 15);     // 0x7FFF per negative half
    uint32_t full = t | m;          // 0xFFFF per negative half
    ah &= ~full;
    al &= ~full;
}

// Bs layout: hi [8 kpairs][132 words], lo at offset 1056.
#define BLO 1056

template<bool RELU>
__device__ __forceinline__ void gemm_tc(
    const uint32_t* At, const float* __restrict__ prep, int nchunks,
    float acc[2][8][4], uint32_t* Bs, int tid, int rb, int nb)
{
    const int lane = tid & 31;
    const int gid = lane >> 2, tig = lane & 3;
    const int srow = tid >> 5, scol4 = (tid & 31) << 2;

    for (int c = 0; c < nchunks; ++c) {
        __syncthreads();
        const float* src = prep + (size_t)c * 2048;
        *(float4*)(Bs + srow*132 + scol4)       = *(const float4*)(src + tid*4);
        *(float4*)(Bs + BLO + srow*132 + scol4) = *(const float4*)(src + 1024 + tid*4);
        __syncthreads();

        const int k8 = c*8;
        uint32_t Ah[2][4], Al[2][4];
#pragma unroll
        for (int mt = 0; mt < 2; ++mt) {
            const uint32_t* ap = At + (size_t)(rb + mt*16 + gid)*AST + k8 + tig;
            Ah[mt][0] = ap[0];
            Ah[mt][1] = ap[8*AST];
            Ah[mt][2] = ap[4];
            Ah[mt][3] = ap[8*AST + 4];
            Al[mt][0] = ap[AIMG];
            Al[mt][1] = ap[AIMG + 8*AST];
            Al[mt][2] = ap[AIMG + 4];
            Al[mt][3] = ap[AIMG + 8*AST + 4];
            if (RELU) {
#pragma unroll
                for (int i = 0; i < 4; ++i)
                    relu_mask(Ah[mt][i], Al[mt][i]);
            }
        }
#pragma unroll
        for (int j = 0; j < 8; ++j) {
            const int n = nb + j*8 + gid;
            uint32_t bh[2], bl[2];
            bh[0] = Bs[tig*132 + n];
            bh[1] = Bs[(tig+4)*132 + n];
            bl[0] = Bs[BLO + tig*132 + n];
            bl[1] = Bs[BLO + (tig+4)*132 + n];
#pragma unroll
            for (int mt = 0; mt < 2; ++mt) {
                MMA_BF16(acc[mt][j], Ah[mt], bh);
                MMA_BF16(acc[mt][j], Al[mt], bh);
                MMA_BF16(acc[mt][j], Ah[mt], bl);
            }
        }
    }
}

// store accumulators into a bf16 hi/lo tile (optionally relu'd first)
template<bool RELU>
__device__ __forceinline__ void store_acc_tile(float acc[2][8][4], uint32_t* tile,
                                               int rb, int nb, int lane)
{
    const int gid = lane >> 2, tig = lane & 3;
#pragma unroll
    for (int mt = 0; mt < 2; ++mt) {
        const int rg = rb + mt*16 + gid;
#pragma unroll
        for (int j = 0; j < 8; ++j) {
            const int w = ((nb + j*8) >> 1) + tig;
            float v0 = acc[mt][j][0], v1 = acc[mt][j][1];
            float v2 = acc[mt][j][2], v3 = acc[mt][j][3];
            if (RELU) {
                v0 = fmaxf(v0, 0.f); v1 = fmaxf(v1, 0.f);
                v2 = fmaxf(v2, 0.f); v3 = fmaxf(v3, 0.f);
            }
            uint32_t wh, wl;
            split2(v0, v1, wh, wl);
            tile[(size_t)rg*AST + w]        = wh;
            tile[AIMG + (size_t)rg*AST + w] = wl;
            split2(v2, v3, wh, wl);
            tile[(size_t)(rg+8)*AST + w]        = wh;
            tile[AIMG + (size_t)(rg+8)*AST + w] = wl;
        }
    }
}

__global__ __launch_bounds__(256) void resnet_tc(
    int blk,
    const float* __restrict__ b0, const float* __restrict__ b1,
    const float* __restrict__ bo, int add_res)
{
    extern __shared__ uint32_t sm[];
    uint32_t* xs  = sm;              // hi+lo images [2*AIMG]
    uint32_t* as_ = sm + 2*AIMG;
    uint32_t* hs  = sm + 4*AIMG;
    uint32_t* Bs  = sm + 6*AIMG;     // hi[8][132] + lo[8][132]

    const int tid = threadIdx.x;
    const int wid = tid >> 5, lane = tid & 31;
    const int rb = (wid & 3) * 32;
    const int nb = (wid >> 2) * 64;
    const int gid = lane >> 2, tig = lane & 3;
    const size_t t0 = (size_t)blockIdx.x * 128;
    const float* prep = g_bprep + (size_t)blk * 48 * 2048;

    // load net -> xs (split), att -> hs (split)
    for (int q = tid; q < 128 * 32; q += 256) {
        int r = q >> 5, c4 = q & 31;          // element col = c4*4, word col = c4*2
        float4 v = *(const float4*)(g_net + (t0 + r) * HH + c4 * 4);
        uint32_t wh0, wl0, wh1, wl1;
        split2(v.x, v.y, wh0, wl0);
        split2(v.z, v.w, wh1, wl1);
        xs[(size_t)r*AST + c4*2]            = wh0;
        xs[(size_t)r*AST + c4*2 + 1]        = wh1;
        xs[AIMG + (size_t)r*AST + c4*2]     = wl0;
        xs[AIMG + (size_t)r*AST + c4*2 + 1] = wl1;
        v = *(const float4*)(g_att + (t0 + r) * HH + c4 * 4);
        split2(v.x, v.y, wh0, wl0);
        split2(v.z, v.w, wh1, wl1);
        hs[(size_t)r*AST + c4*2]            = wh0;
        hs[(size_t)r*AST + c4*2 + 1]        = wh1;
        hs[AIMG + (size_t)r*AST + c4*2]     = wl0;
        hs[AIMG + (size_t)r*AST + c4*2 + 1] = wl1;
    }

    float acc[2][8][4];

    // ---- GEMM1: a1 = att @ Wo^T + bo -> as_ (plain split)
    init_acc(acc, bo, nb, tig);
    gemm_tc<false>(hs, prep + 0*2048, 8, acc, Bs, tid, rb, nb);
    store_acc_tile<false>(acc, as_, rb, nb, lane);

    // ---- GEMM2: h = relu(relu([x|a1]) @ W0 + b0) -> hs (relu'd split)
    init_acc(acc, b0, nb, tig);
    gemm_tc<true>(xs,  prep + 8*2048,  8, acc, Bs, tid, rb, nb);
    gemm_tc<true>(as_, prep + 16*2048, 8, acc, Bs, tid, rb, nb);
    __syncthreads();
    store_acc_tile<true>(acc, hs, rb, nb, lane);

    // ---- GEMM3+4: out = h @ W1^T + b1 + [x|a1] @ Ws^T [+ residual]
    init_acc(acc, b1, nb, tig);
    gemm_tc<false>(hs,  prep + 24*2048, 8, acc, Bs, tid, rb, nb);
    gemm_tc<false>(xs,  prep + 32*2048, 8, acc, Bs, tid, rb, nb);
    gemm_tc<false>(as_, prep + 40*2048, 8, acc, Bs, tid, rb, nb);

#pragma unroll
    for (int mt = 0; mt < 2; ++mt) {
        const int rg = rb + mt*16 + gid;
#pragma unroll
        for (int j = 0; j < 8; ++j) {
            const int col0 = nb + j*8 + 2*tig;
            float v0 = acc[mt][j][0], v1 = acc[mt][j][1];
            float v2 = acc[mt][j][2], v3 = acc[mt][j][3];
            float* d0 = g_net + (t0 + rg) * HH + col0;
            float* d1 = g_net + (t0 + rg + 8) * HH + col0;
            if (add_res) {
                float2 r0 = *(const float2*)d0;
                float2 r1 = *(const float2*)d1;
                v0 += r0.x; v1 += r0.y; v2 += r1.x; v3 += r1.y;
            }
            *(float2*)d0 = make_float2(v0, v1);
            *(float2*)d1 = make_float2(v2, v3);
        }
    }
}

// ======================= final projection (scalar, FFMA2) ===============
__device__ __forceinline__ void init_bias_f(u64 acc[8][4], const float* __restrict__ bias, int nb)
{
    ulonglong2 q0 = *(const ulonglong2*)(bias + nb);
    ulonglong2 q1 = *(const ulonglong2*)(bias + nb + 4);
#pragma unroll
    for (int r = 0; r < 8; ++r) {
        acc[r][0] = q0.x; acc[r][1] = q0.y; acc[r][2] = q1.x; acc[r][3] = q1.y;
    }
}

__global__ __launch_bounds__(256) void final_kernel(const float* __restrict__ W_c,
                                                    const float* __restrict__ b_c,
                                                    float* __restrict__ out)
{
    extern __shared__ float smf[];
    float* xs = smf;             // [128][SX]
    float* ws = smf + 128 * SX;  // [32][128]

    const int tid = threadIdx.x;
    const int tx = tid & 15;
    const int ty = tid >> 4;
    const int nb = tx * 8;
    const int rb = ty * 8;
    const size_t t0 = (size_t)blockIdx.x * 128;

    for (int q = tid; q < 128 * 32; q += 256) {
        int r = q >> 5, c = (q & 31) << 2;
        *(float4*)(xs + r * SX + c) = *(const float4*)(g_net + (t0 + r) * HH + c);
    }

    u64 acc[8][4];
    init_bias_f(acc, b_c, nb);

    for (int kt = 0; kt < 128; kt += 32) {
        __syncthreads();
        for (int q = tid; q < 1024; q += 256) {
            int kk = q >> 5, c = (q & 31) << 2;
            *(float4*)(ws + kk * 128 + c) = *(const float4*)(W_c + (size_t)(kt + kk) * 128 + c);
        }
        __syncthreads();
#pragma unroll 1
        for (int k4 = 0; k4 < 8; ++k4) {
            float4 a4[8];
#pragma unroll
            for (int r = 0; r < 8; ++r)
                a4[r] = *(const float4*)(xs + (rb + r) * SX + kt + k4 * 4);
#pragma unroll
            for (int j = 0; j < 4; ++j) {
                int kk = k4 * 4 + j;
                ulonglong2 b0v = *(const ulonglong2*)(ws + kk * 128 + nb);
                ulonglong2 b1v = *(const ulonglong2*)(ws + kk * 128 + nb + 4);
#pragma unroll
                for (int r = 0; r < 8; ++r) {
                    float a = ((const float*)&a4[r])[j];
                    u64 aa; BCAST2(aa, __float_as_uint(a));
                    FMA2(acc[r][0], aa, b0v.x, acc[r][0]);
                    FMA2(acc[r][1], aa, b0v.y, acc[r][1]);
                    FMA2(acc[r][2], aa, b1v.x, acc[r][2]);
                    FMA2(acc[r][3], aa, b1v.y, acc[r][3]);
                }
            }
        }
    }
#pragma unroll
    for (int r = 0; r < 8; ++r) {
        *(ulonglong2*)(out + (t0 + rb + r) * HH + nb)     = make_ulonglong2(acc[r][0], acc[r][1]);
        *(ulonglong2*)(out + (t0 + rb + r) * HH + nb + 4) = make_ulonglong2(acc[r][2], acc[r][3]);
    }
}

// ======================= launch =========================================
extern "C" void kernel_launch(void* const* d_in, const int* in_sizes, int n_in,
                              void* d_out, int out_size)
{
    const float* p      = (const float*)d_in[0];
    const float* W_pos  = (const float*)d_in[1];
    const float* b_pos  = (const float*)d_in[2];
    const float* blk_W0 = (const float*)d_in[3];
    const float* blk_b0 = (const float*)d_in[4];
    const float* blk_W1 = (const float*)d_in[5];
    const float* blk_b1 = (const float*)d_in[6];
    const float* blk_Ws = (const float*)d_in[7];
    const float* att_Wc = (const float*)d_in[8];
    const float* att_bc = (const float*)d_in[9];
    const float* att_Wo = (const float*)d_in[10];
    const float* att_bo = (const float*)d_in[11];
    const float* W_c    = (const float*)d_in[12];
    const float* b_c    = (const float*)d_in[13];
    float* out = (float*)d_out;

    const int RES_SMEM = (6 * AIMG + 2 * 8 * 132) * 4;   // 217,344 B
    const int FIN_SMEM = (128 * SX + 32 * 128) * 4;      //  83,968 B
    cudaFuncSetAttribute(resnet_tc,   cudaFuncAttributeMaxDynamicSharedMemorySize, RES_SMEM);
    cudaFuncSetAttribute(final_kernel, cudaFuncAttributeMaxDynamicSharedMemorySize, FIN_SMEM);

    prep_weights<<<dim3(48, NBLK), 256>>>(att_Wo, blk_W0, blk_W1, blk_Ws);
    knn_kernel<<<dim3(TT / 128, BB), 128>>>(p);
    pos_kernel<<<(BT * HH) / 256, 256>>>(p, W_pos, b_pos);

    for (int i = 0; i < NBLK; ++i) {
        attn_kernel<<<BT / 8, 256>>>(p, att_Wc + (size_t)i * 7, att_bc + i);
        resnet_tc<<<BT / 128, 256, RES_SMEM>>>(
            i, blk_b0 + (size_t)i * 128, blk_b1 + (size_t)i * 128,
            att_bo + (size_t)i * 128, i > 0 ? 1 : 0);
    }
    final_kernel<<<BT / 128, 256, FIN_SMEM>>>(W_c, b_c, out);
}

// round 11
// speedup vs baseline: 2.0970x; 1.0363x over previous
#include <cuda_runtime.h>
#include <cuda_bf16.h>
#include <math.h>
#include <float.h>
#include <stdint.h>

#define BB 8
#define TT 4096
#define HH 128
#define NBLK 6
#define KK 20
#define BT (BB*TT)   // 32768
#define SX 132       // f32 tile stride (final_kernel only)
#define ATILE 16384  // A image words per tile: 8 chunks x 128 rows x 16 words

typedef unsigned long long u64;

// packed f32x2 helpers (scalar kernels)
#define FMA2(d, a, b, c) \
    asm("fma.rn.f32x2 %0, %1, %2, %3;" : "=l"(d) : "l"(a), "l"(b), "l"(c))
#define BCAST2(d, s) \
    asm("mov.b64 %0, {%1, %1};" : "=l"(d) : "r"(s))

// bf16 mma (sm_80+ PTX, valid at target sm_103)
#define MMA_BF16(d, a, b) \
    asm volatile("mma.sync.aligned.m16n8k16.row.col.f32.bf16.bf16.f32 " \
        "{%0,%1,%2,%3}, {%4,%5,%6,%7}, {%8,%9}, {%0,%1,%2,%3};" \
        : "+f"((d)[0]), "+f"((d)[1]), "+f"((d)[2]), "+f"((d)[3]) \
        : "r"((a)[0]), "r"((a)[1]), "r"((a)[2]), "r"((a)[3]), \
          "r"((b)[0]), "r"((b)[1]))

// pack two f32 into bf16x2: low 16 bits <- vlo, high <- vhi
__device__ __forceinline__ uint32_t pack_bf16x2(float vlo, float vhi) {
    uint32_t r;
    asm("cvt.rn.bf16x2.f32 %0, %1, %2;" : "=r"(r) : "f"(vhi), "f"(vlo));
    return r;
}

// split f32 pair -> (hi word, lo word)
__device__ __forceinline__ void split2(float x, float y, uint32_t& wh, uint32_t& wl) {
    wh = pack_bf16x2(x, y);
    float h0 = __uint_as_float(wh << 16);
    float h1 = __uint_as_float(wh & 0xffff0000u);
    wl = pack_bf16x2(x - h0, y - h1);
}

// ---------------- scratch (device globals; no allocation) ----------------
__device__ float g_net[BT * HH];   // 16 MB
__device__ float g_att[BT * HH];   // 16 MB
__device__ int   g_idx[BT * KK];
__device__ float g_dis[BT * KK];
// prepped weights: per block 48 K16-chunks x 2048 quad-packed words
__device__ float g_bprep[NBLK * 48 * 2048];   // 2.4 MB

// ======================= KNN (scalar, proven) ===========================
__global__ __launch_bounds__(128) void knn_kernel(const float* __restrict__ p)
{
    const int b  = blockIdx.y;
    const int tt = blockIdx.x * 128 + threadIdx.x;
    const float* pb = p + (size_t)b * TT * 3;

    const float qx = pb[tt*3 + 0];
    const float qy = pb[tt*3 + 1];
    const float qz = pb[tt*3 + 2];
    const float sqq = (qx*qx + qy*qy) + qz*qz;

    float bd[KK];
    int   bi[KK];
#pragma unroll
    for (int k = 0; k < KK; ++k) { bd[k] = FLT_MAX; bi[k] = 0; }

    __shared__ float4 sp[1024];   // x,y,z,|.|^2

    for (int s0 = 0; s0 < TT; s0 += 1024) {
        __syncthreads();
        for (int l = threadIdx.x; l < 1024; l += 128) {
            const float* q = pb + (size_t)(s0 + l) * 3;
            float x = q[0], y = q[1], z = q[2];
            sp[l] = make_float4(x, y, z, (x*x + y*y) + z*z);
        }
        __syncthreads();
#pragma unroll 4
        for (int l = 0; l < 1024; ++l) {
            float4 v = sp[l];
            float dot = qx*v.x + qy*v.y + qz*v.z;
            float d2  = sqq + v.w - 2.0f * dot;
            if (d2 < bd[KK-1]) {
                bd[KK-1] = d2; bi[KK-1] = s0 + l;
#pragma unroll
                for (int q2 = KK-1; q2 > 0; --q2) {
                    if (bd[q2] < bd[q2-1]) {
                        float td = bd[q2]; bd[q2] = bd[q2-1]; bd[q2-1] = td;
                        int   ti = bi[q2]; bi[q2] = bi[q2-1]; bi[q2-1] = ti;
                    }
                }
            }
        }
    }

    const size_t o = ((size_t)b * TT + tt) * KK;
#pragma unroll
    for (int k = 0; k < KK; ++k) {
        g_idx[o + k] = bi[k];
        g_dis[o + k] = sqrtf(fmaxf(bd[k], 1e-12f));
    }
}

// ======================= positional encoding ============================
__global__ __launch_bounds__(256) void pos_kernel(const float* __restrict__ p,
                                                  const float* __restrict__ W_pos,
                                                  const float* __restrict__ b_pos)
{
    int gid = blockIdx.x * 256 + threadIdx.x;
    int t = gid >> 7;
    int h = gid & 127;
    const float* pp = p + (size_t)t * 3;
    float v = b_pos[h];
    v = fmaf(pp[0], W_pos[h],        v);
    v = fmaf(pp[1], W_pos[HH + h],   v);
    v = fmaf(pp[2], W_pos[2*HH + h], v);
    g_net[gid] = v;
}

// ======================= attention (gather + softmax) ===================
__global__ __launch_bounds__(256) void attn_kernel(const float* __restrict__ p,
                                                   const float* __restrict__ wc,
                                                   const float* __restrict__ bc)
{
    const int warp = threadIdx.x >> 5;
    const int lane = threadIdx.x & 31;
    const int t  = blockIdx.x * 8 + warp;
    const int b  = t >> 12;
    const int tt = t & (TT - 1);
    const float* pb = p + (size_t)b * TT * 3;

    const float q0 = pb[tt*3+0], q1 = pb[tt*3+1], q2 = pb[tt*3+2];
    const float w0 = wc[0], w1 = wc[1], w2 = wc[2], w3 = wc[3];
    const float w4 = wc[4], w5 = wc[5], w6 = wc[6], bcv = bc[0];

    float s = -FLT_MAX;
    int   j = 0;
    if (lane < KK) {
        size_t o = (size_t)t * KK + lane;
        j = g_idx[o];
        float d = g_dis[o];
        const float* px = pb + (size_t)j * 3;
        s = bcv;
        s = fmaf(w0, d,     s);
        s = fmaf(w1, px[0], s);
        s = fmaf(w2, px[1], s);
        s = fmaf(w3, px[2], s);
        s = fmaf(w4, q0,    s);
        s = fmaf(w5, q1,    s);
        s = fmaf(w6, q2,    s);
    }
    float m = s;
#pragma unroll
    for (int off = 16; off; off >>= 1)
        m = fmaxf(m, __shfl_xor_sync(0xffffffffu, m, off));
    float e = (lane < KK) ? expf(s - m) : 0.0f;
    float sum = e;
#pragma unroll
    for (int off = 16; off; off >>= 1)
        sum += __shfl_xor_sync(0xffffffffu, sum, off);
    const float inv = 1.0f / sum;

    float4 acc = make_float4(0.f, 0.f, 0.f, 0.f);
    const float* nb = g_net + (size_t)b * TT * HH;
#pragma unroll
    for (int k = 0; k < KK; ++k) {
        float wk = __shfl_sync(0xffffffffu, e, k) * inv;
        int   jk = __shfl_sync(0xffffffffu, j, k);
        float4 v = *(const float4*)(nb + (size_t)jk * HH + lane * 4);
        acc.x = fmaf(wk, v.x, acc.x);
        acc.y = fmaf(wk, v.y, acc.y);
        acc.z = fmaf(wk, v.z, acc.z);
        acc.w = fmaf(wk, v.w, acc.w);
    }
    *(float4*)(g_att + (size_t)t * HH + lane * 4) = acc;
}

// ======================= weight prep (quad-packed bf16) ==================
// 48 K16-chunk slots per block: Wo 0..7, W0 8..23, W1 24..31, Ws 32..47.
// Chunk image (2048 words): idx = n*16 + t*4 + {hi_t, hi_{t+4}, lo_t, lo_{t+4}}
// where word hi_t = bf16x2 of (W[ck*16+2t][n], W[ck*16+2t+1][n]).
__global__ __launch_bounds__(256) void prep_weights(
    const float* __restrict__ Wo, const float* __restrict__ W0,
    const float* __restrict__ W1, const float* __restrict__ Ws)
{
    const int blk = blockIdx.y;
    const int slot = blockIdx.x;
    const float* W; int ck;
    if (slot < 8)       { W = Wo + (size_t)blk*128*128; ck = slot; }
    else if (slot < 24) { W = W0 + (size_t)blk*256*128; ck = slot-8; }
    else if (slot < 32) { W = W1 + (size_t)blk*128*128; ck = slot-24; }
    else                { W = Ws + (size_t)blk*256*128; ck = slot-32; }
    float* img = g_bprep + ((size_t)blk*48 + slot)*2048;

    for (int it = threadIdx.x; it < 512; it += 256) {
        int n = it >> 2, t = it & 3;
        int k0 = ck*16 + 2*t;
        float a0 = W[(size_t)k0*128 + n];
        float a1 = W[(size_t)(k0+1)*128 + n];
        float a2 = W[(size_t)(k0+8)*128 + n];
        float a3 = W[(size_t)(k0+9)*128 + n];
        uint32_t h0, l0, h1, l1;
        split2(a0, a1, h0, l0);
        split2(a2, a3, h1, l1);
        uint4 q = make_uint4(h0, h1, l0, l1);
        *(uint4*)(img + n*16 + t*4) = q;
    }
}

// ======================= tensor-core resnet (quad-packed) ================
__device__ __forceinline__ void init_acc(float acc[2][8][4],
                                         const float* __restrict__ bias,
                                         int nb, int tig)
{
#pragma unroll
    for (int j = 0; j < 8; ++j) {
        int col0 = nb + j*8 + 2*tig;
        float b0v = __ldg(bias + col0);
        float b1v = __ldg(bias + col0 + 1);
#pragma unroll
        for (int mt = 0; mt < 2; ++mt) {
            acc[mt][j][0] = b0v; acc[mt][j][1] = b1v;
            acc[mt][j][2] = b0v; acc[mt][j][3] = b1v;
        }
    }
}

// zero both hi/lo halves of the split where the hi half is negative
__device__ __forceinline__ void relu_mask(uint32_t& ah, uint32_t& al)
{
    uint32_t t = ah & 0x80008000u;
    uint32_t m = t - (t >> 15);     // 0x7FFF per negative half
    uint32_t full = t | m;          // 0xFFFF per negative half
    ah &= ~full;
    al &= ~full;
}

// A image layout: word addr = c*2048 + row*16 + t*4 + {h_t, h_{t+4}, l_t, l_{t+4}}
// Bs (double-buffered): buf words = n*16 + t*4 + {bh_t, bh_{t+4}, bl_t, bl_{t+4}}
template<bool RELU>
__device__ __forceinline__ void gemm_tc(
    const uint32_t* At, const float* __restrict__ prep, int nchunks,
    float acc[2][8][4], uint32_t* Bs, int tid, int rb, int nb)
{
    const int lane = tid & 31;
    const int gid = lane >> 2, tig = lane & 3;

    // stage chunk 0
    __syncthreads();
    {
        const float4* s = (const float4*)prep;
        *(float4*)(Bs + tid*4)        = s[tid];
        *(float4*)(Bs + 1024 + tid*4) = s[tid + 256];
    }
    __syncthreads();

    for (int c = 0; c < nchunks; ++c) {
        const uint32_t* buf = Bs + (c & 1) * 2048;
        float4 pre0, pre1;
        if (c + 1 < nchunks) {
            const float4* s = (const float4*)(prep + (size_t)(c+1) * 2048);
            pre0 = s[tid];
            pre1 = s[tid + 256];
        }

        uint32_t Ah[2][4], Al[2][4];
#pragma unroll
        for (int mt = 0; mt < 2; ++mt) {
            const uint32_t* ap = At + (size_t)c*2048 + (rb + mt*16 + gid)*16 + tig*4;
            uint4 qa = *(const uint4*)ap;
            uint4 qb = *(const uint4*)(ap + 128);   // row + 8
            Ah[mt][0] = qa.x; Ah[mt][2] = qa.y; Al[mt][0] = qa.z; Al[mt][2] = qa.w;
            Ah[mt][1] = qb.x; Ah[mt][3] = qb.y; Al[mt][1] = qb.z; Al[mt][3] = qb.w;
            if (RELU) {
#pragma unroll
                for (int i = 0; i < 4; ++i)
                    relu_mask(Ah[mt][i], Al[mt][i]);
            }
        }
#pragma unroll
        for (int j = 0; j < 8; ++j) {
            const int n = nb + j*8 + gid;
            uint4 q = *(const uint4*)(buf + n*16 + tig*4);
            uint32_t bh[2] = { q.x, q.y };
            uint32_t bl[2] = { q.z, q.w };
#pragma unroll
            for (int mt = 0; mt < 2; ++mt) {
                MMA_BF16(acc[mt][j], Ah[mt], bh);
                MMA_BF16(acc[mt][j], Al[mt], bh);
                MMA_BF16(acc[mt][j], Ah[mt], bl);
            }
        }
        if (c + 1 < nchunks) {
            uint32_t* nbuf = Bs + ((c+1) & 1) * 2048;
            *(float4*)(nbuf + tid*4)        = pre0;
            *(float4*)(nbuf + 1024 + tid*4) = pre1;
        }
        __syncthreads();
    }
}

// store accumulators into a quad-packed bf16 tile (optionally relu'd first)
template<bool RELU>
__device__ __forceinline__ void store_acc_tile(float acc[2][8][4], uint32_t* tile,
                                               int rb, int nb, int lane)
{
    const int gid = lane >> 2, tig = lane & 3;
#pragma unroll
    for (int mt = 0; mt < 2; ++mt) {
        const int rg = rb + mt*16 + gid;
#pragma unroll
        for (int j = 0; j < 8; ++j) {
            const int kp = (nb >> 1) + j*4 + tig;     // global kpair 0..63
            const int c = kp >> 3, tq = kp & 7;
            const int base = c*2048 + (tq & 3)*4 + (tq >> 2);
            float v0 = acc[mt][j][0], v1 = acc[mt][j][1];
            float v2 = acc[mt][j][2], v3 = acc[mt][j][3];
            if (RELU) {
                v0 = fmaxf(v0, 0.f); v1 = fmaxf(v1, 0.f);
                v2 = fmaxf(v2, 0.f); v3 = fmaxf(v3, 0.f);
            }
            uint32_t wh, wl;
            split2(v0, v1, wh, wl);
            tile[base + rg*16]     = wh;
            tile[base + rg*16 + 2] = wl;
            split2(v2, v3, wh, wl);
            tile[base + (rg+8)*16]     = wh;
            tile[base + (rg+8)*16 + 2] = wl;
        }
    }
}

__global__ __launch_bounds__(256) void resnet_tc(
    int blk,
    const float* __restrict__ b0, const float* __restrict__ b1,
    const float* __restrict__ bo, int add_res)
{
    extern __shared__ uint32_t sm[];
    uint32_t* xs  = sm;               // [ATILE]
    uint32_t* as_ = sm + ATILE;
    uint32_t* hs  = sm + 2*ATILE;
    uint32_t* Bs  = sm + 3*ATILE;     // 2 x 2048 double buffer

    const int tid = threadIdx.x;
    const int wid = tid >> 5, lane = tid & 31;
    const int rb = (wid & 3) * 32;
    const int nb = (wid >> 2) * 64;
    const int gid = lane >> 2, tig = lane & 3;
    const size_t t0 = (size_t)blockIdx.x * 128;
    const float* prep = g_bprep + (size_t)blk * 48 * 2048;

    // build xs (net) and hs (att) quad-packed images
    for (int it = tid; it < 4096; it += 256) {
        int r = it >> 5, rem = it & 31;
        int c = rem >> 2, t = rem & 3;
        int e0 = 16*c + 2*t;
        const float* src = g_net + (t0 + r) * HH;
        float2 p0 = *(const float2*)(src + e0);
        float2 p1 = *(const float2*)(src + e0 + 8);
        uint32_t h0, l0, h1, l1;
        split2(p0.x, p0.y, h0, l0);
        split2(p1.x, p1.y, h1, l1);
        *(uint4*)(xs + c*2048 + r*16 + t*4) = make_uint4(h0, h1, l0, l1);
        src = g_att + (t0 + r) * HH;
        p0 = *(const float2*)(src + e0);
        p1 = *(const float2*)(src + e0 + 8);
        split2(p0.x, p0.y, h0, l0);
        split2(p1.x, p1.y, h1, l1);
        *(uint4*)(hs + c*2048 + r*16 + t*4) = make_uint4(h0, h1, l0, l1);
    }

    float acc[2][8][4];

    // ---- GEMM1: a1 = att @ Wo^T + bo -> as_ (plain split)
    init_acc(acc, bo, nb, tig);
    gemm_tc<false>(hs, prep + 0*2048, 8, acc, Bs, tid, rb, nb);
    store_acc_tile<false>(acc, as_, rb, nb, lane);

    // ---- GEMM2: h = relu(relu([x|a1]) @ W0 + b0) -> hs (relu'd split)
    init_acc(acc, b0, nb, tig);
    gemm_tc<true>(xs,  prep + 8*2048,  8, acc, Bs, tid, rb, nb);
    gemm_tc<true>(as_, prep + 16*2048, 8, acc, Bs, tid, rb, nb);
    __syncthreads();
    store_acc_tile<true>(acc, hs, rb, nb, lane);

    // ---- GEMM3+4: out = h @ W1^T + b1 + [x|a1] @ Ws^T [+ residual]
    init_acc(acc, b1, nb, tig);
    gemm_tc<false>(hs,  prep + 24*2048, 8, acc, Bs, tid, rb, nb);
    gemm_tc<false>(xs,  prep + 32*2048, 8, acc, Bs, tid, rb, nb);
    gemm_tc<false>(as_, prep + 40*2048, 8, acc, Bs, tid, rb, nb);

#pragma unroll
    for (int mt = 0; mt < 2; ++mt) {
        const int rg = rb + mt*16 + gid;
#pragma unroll
        for (int j = 0; j < 8; ++j) {
            const int col0 = nb + j*8 + 2*tig;
            float v0 = acc[mt][j][0], v1 = acc[mt][j][1];
            float v2 = acc[mt][j][2], v3 = acc[mt][j][3];
            float* d0 = g_net + (t0 + rg) * HH + col0;
            float* d1 = g_net + (t0 + rg + 8) * HH + col0;
            if (add_res) {
                float2 r0 = *(const float2*)d0;
                float2 r1 = *(const float2*)d1;
                v0 += r0.x; v1 += r0.y; v2 += r1.x; v3 += r1.y;
            }
            *(float2*)d0 = make_float2(v0, v1);
            *(float2*)d1 = make_float2(v2, v3);
        }
    }
}

// ======================= final projection (scalar, FFMA2) ===============
__device__ __forceinline__ void init_bias_f(u64 acc[8][4], const float* __restrict__ bias, int nb)
{
    ulonglong2 q0 = *(const ulonglong2*)(bias + nb);
    ulonglong2 q1 = *(const ulonglong2*)(bias + nb + 4);
#pragma unroll
    for (int r = 0; r < 8; ++r) {
        acc[r][0] = q0.x; acc[r][1] = q0.y; acc[r][2] = q1.x; acc[r][3] = q1.y;
    }
}

__global__ __launch_bounds__(256) void final_kernel(const float* __restrict__ W_c,
                                                    const float* __restrict__ b_c,
                                                    float* __restrict__ out)
{
    extern __shared__ float smf[];
    float* xs = smf;             // [128][SX]
    float* ws = smf + 128 * SX;  // [32][128]

    const int tid = threadIdx.x;
    const int tx = tid & 15;
    const int ty = tid >> 4;
    const int nb = tx * 8;
    const int rb = ty * 8;
    const size_t t0 = (size_t)blockIdx.x * 128;

    for (int q = tid; q < 128 * 32; q += 256) {
        int r = q >> 5, c = (q & 31) << 2;
        *(float4*)(xs + r * SX + c) = *(const float4*)(g_net + (t0 + r) * HH + c);
    }

    u64 acc[8][4];
    init_bias_f(acc, b_c, nb);

    for (int kt = 0; kt < 128; kt += 32) {
        __syncthreads();
        for (int q = tid; q < 1024; q += 256) {
            int kk = q >> 5, c = (q & 31) << 2;
            *(float4*)(ws + kk * 128 + c) = *(const float4*)(W_c + (size_t)(kt + kk) * 128 + c);
        }
        __syncthreads();
#pragma unroll 1
        for (int k4 = 0; k4 < 8; ++k4) {
            float4 a4[8];
#pragma unroll
            for (int r = 0; r < 8; ++r)
                a4[r] = *(const float4*)(xs + (rb + r) * SX + kt + k4 * 4);
#pragma unroll
            for (int j = 0; j < 4; ++j) {
                int kk = k4 * 4 + j;
                ulonglong2 b0v = *(const ulonglong2*)(ws + kk * 128 + nb);
                ulonglong2 b1v = *(const ulonglong2*)(ws + kk * 128 + nb + 4);
#pragma unroll
                for (int r = 0; r < 8; ++r) {
                    float a = ((const float*)&a4[r])[j];
                    u64 aa; BCAST2(aa, __float_as_uint(a));
                    FMA2(acc[r][0], aa, b0v.x, acc[r][0]);
                    FMA2(acc[r][1], aa, b0v.y, acc[r][1]);
                    FMA2(acc[r][2], aa, b1v.x, acc[r][2]);
                    FMA2(acc[r][3], aa, b1v.y, acc[r][3]);
                }
            }
        }
    }
#pragma unroll
    for (int r = 0; r < 8; ++r) {
        *(ulonglong2*)(out + (t0 + rb + r) * HH + nb)     = make_ulonglong2(acc[r][0], acc[r][1]);
        *(ulonglong2*)(out + (t0 + rb + r) * HH + nb + 4) = make_ulonglong2(acc[r][2], acc[r][3]);
    }
}

// ======================= launch =========================================
extern "C" void kernel_launch(void* const* d_in, const int* in_sizes, int n_in,
                              void* d_out, int out_size)
{
    const float* p      = (const float*)d_in[0];
    const float* W_pos  = (const float*)d_in[1];
    const float* b_pos  = (const float*)d_in[2];
    const float* blk_W0 = (const float*)d_in[3];
    const float* blk_b0 = (const float*)d_in[4];
    const float* blk_W1 = (const float*)d_in[5];
    const float* blk_b1 = (const float*)d_in[6];
    const float* blk_Ws = (const float*)d_in[7];
    const float* att_Wc = (const float*)d_in[8];
    const float* att_bc = (const float*)d_in[9];
    const float* att_Wo = (const float*)d_in[10];
    const float* att_bo = (const float*)d_in[11];
    const float* W_c    = (const float*)d_in[12];
    const float* b_c    = (const float*)d_in[13];
    float* out = (float*)d_out;

    const int RES_SMEM = (3 * ATILE + 2 * 2048) * 4;   // 212,992 B
    const int FIN_SMEM = (128 * SX + 32 * 128) * 4;    //  83,968 B
    cudaFuncSetAttribute(resnet_tc,   cudaFuncAttributeMaxDynamicSharedMemorySize, RES_SMEM);
    cudaFuncSetAttribute(final_kernel, cudaFuncAttributeMaxDynamicSharedMemorySize, FIN_SMEM);

    prep_weights<<<dim3(48, NBLK), 256>>>(att_Wo, blk_W0, blk_W1, blk_Ws);
    knn_kernel<<<dim3(TT / 128, BB), 128>>>(p);
    pos_kernel<<<(BT * HH) / 256, 256>>>(p, W_pos, b_pos);

    for (int i = 0; i < NBLK; ++i) {
        attn_kernel<<<BT / 8, 256>>>(p, att_Wc + (size_t)i * 7, att_bc + i);
        resnet_tc<<<BT / 128, 256, RES_SMEM>>>(
            i, blk_b0 + (size_t)i * 128, blk_b1 + (size_t)i * 128,
            att_bo + (size_t)i * 128, i > 0 ? 1 : 0);
    }
    final_kernel<<<BT / 128, 256, FIN_SMEM>>>(W_c, b_c, out);
}